// round 1
// baseline (speedup 1.0000x reference)
#include <cuda_runtime.h>
#include <math.h>

#define D_MODEL 512
#define NHEAD   8
#define HD      64
#define Tn      1552
#define Bn      4
#define BT      (Bn*Tn)     // 6208
#define HIDDEN  2048
#define L0c     1024
#define LTc     1536
#define CLSc    1551

// ---------------- scratch (static device arrays; no runtime alloc) -------------
__device__ float g_xn  [BT*D_MODEL];
__device__ float g_q   [BT*D_MODEL];
__device__ float g_k   [BT*D_MODEL];
__device__ float g_v   [BT*D_MODEL];
__device__ float g_o   [BT*D_MODEL];
__device__ float g_gate[BT*D_MODEL];
__device__ float g_x1  [BT*D_MODEL];
__device__ float g_xn2 [BT*D_MODEL];
__device__ float g_ha  [BT*HIDDEN];
__device__ float g_hb  [BT*HIDDEN];
__device__ float g_cos [Tn*HD];
__device__ float g_sin [Tn*HD];

// ---------------- RoPE tables --------------------------------------------------
__global__ void rope_init_kernel(float* __restrict__ c, float* __restrict__ s) {
    int t = blockIdx.x, d = threadIdx.x;   // d in [0,64)
    int i = d & 31;
    float invf = powf(10000.f, -(float)i * (1.f/32.f));
    float ph = (float)t * invf;
    c[t*HD + d] = cosf(ph);
    s[t*HD + d] = sinf(ph);
}

// ---------------- LayerNorm (row per block, 128 threads, D=512) ----------------
__global__ void ln_kernel(const float* __restrict__ x, const float* __restrict__ g,
                          const float* __restrict__ b, float* __restrict__ y) {
    int row = blockIdx.x;
    int tid = threadIdx.x;                 // 128 threads * 4 = 512
    const float4* xr = (const float4*)(x + (size_t)row*D_MODEL);
    float4 v = xr[tid];
    float s  = v.x + v.y + v.z + v.w;
    float ss = v.x*v.x + v.y*v.y + v.z*v.z + v.w*v.w;
    __shared__ float r0[4], r1[4];
    #pragma unroll
    for (int o = 16; o; o >>= 1) {
        s  += __shfl_xor_sync(0xFFFFFFFFu, s,  o);
        ss += __shfl_xor_sync(0xFFFFFFFFu, ss, o);
    }
    if ((tid & 31) == 0) { r0[tid>>5] = s; r1[tid>>5] = ss; }
    __syncthreads();
    s  = r0[0] + r0[1] + r0[2] + r0[3];
    ss = r1[0] + r1[1] + r1[2] + r1[3];
    float mu  = s  * (1.f/D_MODEL);
    float var = ss * (1.f/D_MODEL) - mu*mu;
    float inv = rsqrtf(var + 1e-5f);
    float4 gg = ((const float4*)g)[tid];
    float4 bb = ((const float4*)b)[tid];
    float4 o;
    o.x = (v.x-mu)*inv*gg.x + bb.x;
    o.y = (v.y-mu)*inv*gg.y + bb.y;
    o.z = (v.z-mu)*inv*gg.z + bb.z;
    o.w = (v.w-mu)*inv*gg.w + bb.w;
    ((float4*)(y + (size_t)row*D_MODEL))[tid] = o;
}

// ---------------- SGEMM: C = A@W (+bias) (+residual) ---------------------------
// BM=BN=128, BK=8, 256 threads, TM=TN=8. M guarded; N,K assumed multiples of 128/8.
#define GBM 128
#define GBN 128
#define GBK 8
__global__ __launch_bounds__(256)
void sgemm_kernel(const float* __restrict__ A, const float* __restrict__ W,
                  const float* __restrict__ bias, const float* __restrict__ res,
                  float* __restrict__ C, int M, int N, int K) {
    __shared__ float As[GBK][GBM];
    __shared__ float Bs[GBK][GBN];
    int tid = threadIdx.x;
    int bm = blockIdx.y * GBM;
    int bn = blockIdx.x * GBN;
    int tx = tid & 15, ty = tid >> 4;
    float acc[8][8];
    #pragma unroll
    for (int i = 0; i < 8; i++)
        #pragma unroll
        for (int j = 0; j < 8; j++) acc[i][j] = 0.f;

    int arow = tid >> 1;            // 0..127
    int acol = (tid & 1) * 4;       // 0 or 4
    int brow = tid >> 5;            // 0..7
    int bcol = (tid & 31) * 4;      // 0..124

    for (int k0 = 0; k0 < K; k0 += GBK) {
        float4 av = make_float4(0.f, 0.f, 0.f, 0.f);
        if (bm + arow < M)
            av = *(const float4*)(A + (size_t)(bm + arow) * K + k0 + acol);
        As[acol+0][arow] = av.x; As[acol+1][arow] = av.y;
        As[acol+2][arow] = av.z; As[acol+3][arow] = av.w;
        *(float4*)&Bs[brow][bcol] =
            *(const float4*)(W + (size_t)(k0 + brow) * N + bn + bcol);
        __syncthreads();
        #pragma unroll
        for (int kk = 0; kk < GBK; kk++) {
            float4 a0 = *(const float4*)&As[kk][ty*8];
            float4 a1 = *(const float4*)&As[kk][ty*8 + 4];
            float4 b0 = *(const float4*)&Bs[kk][tx*8];
            float4 b1 = *(const float4*)&Bs[kk][tx*8 + 4];
            float ra[8] = {a0.x,a0.y,a0.z,a0.w,a1.x,a1.y,a1.z,a1.w};
            float rb[8] = {b0.x,b0.y,b0.z,b0.w,b1.x,b1.y,b1.z,b1.w};
            #pragma unroll
            for (int i = 0; i < 8; i++)
                #pragma unroll
                for (int j = 0; j < 8; j++)
                    acc[i][j] += ra[i] * rb[j];
        }
        __syncthreads();
    }
    #pragma unroll
    for (int i = 0; i < 8; i++) {
        int row = bm + ty*8 + i;
        if (row >= M) break;
        #pragma unroll
        for (int j = 0; j < 8; j++) {
            int col = bn + tx*8 + j;
            float vv = acc[i][j];
            if (bias) vv += bias[col];
            if (res)  vv += res[(size_t)row * N + col];
            C[(size_t)row * N + col] = vv;
        }
    }
}

// ---------------- RoPE apply (in place, q & k) ----------------------------------
__global__ void rope_apply_kernel(float* __restrict__ q, float* __restrict__ k,
                                  const float* __restrict__ cosb,
                                  const float* __restrict__ sinb) {
    int t = blockIdx.x, b = blockIdx.y;
    int tid = threadIdx.x;                 // 512 = h*64+d
    int d = tid & 63;
    size_t base  = ((size_t)b*Tn + t)*D_MODEL + tid;
    size_t pbase = ((size_t)b*Tn + t)*D_MODEL + (tid & ~63) + ((d < 32) ? d + 32 : d - 32);
    float c = cosb[t*HD + d], s = sinb[t*HD + d];
    float qv = q[base],  kv = k[base];
    float qp = q[pbase], kp = k[pbase];
    float sg = (d < 32) ? -1.f : 1.f;
    __syncthreads();                       // all partner reads done before writes
    q[base] = qv*c + sg*qp*s;
    k[base] = kv*c + sg*kp*s;
}

// ---------------- mask predicate ------------------------------------------------
__device__ __forceinline__ bool allowed_fn(int qi, int j, int s0, int s1) {
    int qd = (qi < L0c) ? 0 : (qi < LTc ? 1 : (qi < CLSc ? 2 : 3));
    if (j < L0c)       return (j < s0)          && ((qd == 0 && j <= qi) || qd >= 2);
    else if (j < LTc)  return ((j - L0c) < s1)  && ((qd == 1 && j <= qi) || qd >= 2);
    else if (j < CLSc) return true;            // NS keys reachable by everyone
    else               return qd == 3;         // only CLS attends CLS
}

// ---------------- attention: BQ=32 rows, 32-key chunks, online softmax ----------
__global__ __launch_bounds__(256)
void attn_kernel(const float* __restrict__ q, const float* __restrict__ k,
                 const float* __restrict__ v,
                 const int* __restrict__ sl0p, const int* __restrict__ sl1p,
                 float* __restrict__ o) {
    int qb = blockIdx.x, h = blockIdx.y, b = blockIdx.z;
    int tid = threadIdx.x;                 // 256
    __shared__ float qs[32][68];
    __shared__ float ks[32][68];
    __shared__ float vs[32][68];
    __shared__ float ps[32][33];
    const int s0 = sl0p[b], s1 = sl1p[b];
    const size_t hb = (size_t)b * Tn * D_MODEL + (size_t)h * HD;
    int q0 = qb * 32;

    {   // load Q tile (2048 floats, 8 per thread)
        int r = tid >> 3, c4 = (tid & 7) * 8;
        int qi = q0 + r;
        float4 z = make_float4(0.f,0.f,0.f,0.f);
        if (qi < Tn) {
            const float4* src = (const float4*)(q + hb + (size_t)qi*D_MODEL + c4);
            *(float4*)&qs[r][c4]     = src[0];
            *(float4*)&qs[r][c4 + 4] = src[1];
        } else {
            *(float4*)&qs[r][c4]     = z;
            *(float4*)&qs[r][c4 + 4] = z;
        }
    }

    int row = tid >> 3;                    // 0..31 (query row within tile)
    int kc  = tid & 7;                     // key sub-column
    int dg  = (tid & 7) * 8;               // d-slice for accumulation
    int myq = q0 + row;
    float m_run = -1e30f, l_run = 0.f;
    float acc[8];
    #pragma unroll
    for (int i = 0; i < 8; i++) acc[i] = 0.f;

    for (int c0 = 0; c0 < Tn; c0 += 32) {
        {   // stage K,V chunk
            int r = tid >> 3, c4 = (tid & 7) * 8;
            int j = c0 + r;
            float4 z = make_float4(0.f,0.f,0.f,0.f);
            if (j < Tn) {
                const float4* ksrc = (const float4*)(k + hb + (size_t)j*D_MODEL + c4);
                const float4* vsrc = (const float4*)(v + hb + (size_t)j*D_MODEL + c4);
                *(float4*)&ks[r][c4]     = ksrc[0];
                *(float4*)&ks[r][c4 + 4] = ksrc[1];
                *(float4*)&vs[r][c4]     = vsrc[0];
                *(float4*)&vs[r][c4 + 4] = vsrc[1];
            } else {
                *(float4*)&ks[r][c4] = z; *(float4*)&ks[r][c4+4] = z;
                *(float4*)&vs[r][c4] = z; *(float4*)&vs[r][c4+4] = z;
            }
        }
        __syncthreads();

        // scores: this thread handles keys jj = kc + u*8, u=0..3
        float dot[4] = {0.f, 0.f, 0.f, 0.f};
        #pragma unroll
        for (int i2 = 0; i2 < 16; i2++) {
            float4 qv = *(const float4*)&qs[row][i2*4];
            #pragma unroll
            for (int u = 0; u < 4; u++) {
                float4 kv = *(const float4*)&ks[kc + u*8][i2*4];
                dot[u] += qv.x*kv.x + qv.y*kv.y + qv.z*kv.z + qv.w*kv.w;
            }
        }
        float sreg[4];
        #pragma unroll
        for (int u = 0; u < 4; u++) {
            int j = c0 + kc + u*8;
            bool ok = (j < Tn) && (myq < Tn) && allowed_fn(myq, j, s0, s1);
            sreg[u] = ok ? dot[u] * 0.125f : -1e9f;
        }
        // per-row reduce over the 8 lanes of this row (lanes differ only in kc)
        float cmax = fmaxf(fmaxf(sreg[0], sreg[1]), fmaxf(sreg[2], sreg[3]));
        #pragma unroll
        for (int ofs = 4; ofs; ofs >>= 1)
            cmax = fmaxf(cmax, __shfl_xor_sync(0xFFFFFFFFu, cmax, ofs));
        float m_new = fmaxf(m_run, cmax);
        float scale = __expf(m_run - m_new);
        float csum = 0.f;
        #pragma unroll
        for (int u = 0; u < 4; u++) {
            float p = __expf(sreg[u] - m_new);
            csum += p;
            ps[row][kc + u*8] = p;
        }
        #pragma unroll
        for (int ofs = 4; ofs; ofs >>= 1)
            csum += __shfl_xor_sync(0xFFFFFFFFu, csum, ofs);
        l_run = l_run * scale + csum;
        m_run = m_new;
        __syncwarp();                      // ps produced/consumed within the warp

        #pragma unroll
        for (int i = 0; i < 8; i++) acc[i] *= scale;
        for (int jj = 0; jj < 32; jj++) {
            float p = ps[row][jj];
            float4 v0 = *(const float4*)&vs[jj][dg];
            float4 v1 = *(const float4*)&vs[jj][dg + 4];
            acc[0] += p*v0.x; acc[1] += p*v0.y; acc[2] += p*v0.z; acc[3] += p*v0.w;
            acc[4] += p*v1.x; acc[5] += p*v1.y; acc[6] += p*v1.z; acc[7] += p*v1.w;
        }
        __syncthreads();                   // protect ks/vs before next stage
    }

    if (myq < Tn) {
        float inv = 1.f / l_run;
        float* dst = o + hb + (size_t)myq*D_MODEL + dg;
        float4 o0 = make_float4(acc[0]*inv, acc[1]*inv, acc[2]*inv, acc[3]*inv);
        float4 o1 = make_float4(acc[4]*inv, acc[5]*inv, acc[6]*inv, acc[7]*inv);
        *(float4*)(dst)     = o0;
        *(float4*)(dst + 4) = o1;
    }
}

// ---------------- elementwise --------------------------------------------------
__global__ void mul_kernel(float* __restrict__ a, const float* __restrict__ b, int n4) {
    int i = blockIdx.x*blockDim.x + threadIdx.x;
    if (i >= n4) return;
    float4 x = ((const float4*)a)[i]; float4 y = ((const float4*)b)[i];
    x.x *= y.x; x.y *= y.y; x.z *= y.z; x.w *= y.w;
    ((float4*)a)[i] = x;
}
__global__ void silu_mul_kernel(float* __restrict__ a, const float* __restrict__ b, int n4) {
    int i = blockIdx.x*blockDim.x + threadIdx.x;
    if (i >= n4) return;
    float4 x = ((const float4*)a)[i]; float4 y = ((const float4*)b)[i];
    x.x = x.x / (1.f + __expf(-x.x)) * y.x;
    x.y = x.y / (1.f + __expf(-x.y)) * y.y;
    x.z = x.z / (1.f + __expf(-x.z)) * y.z;
    x.w = x.w / (1.f + __expf(-x.w)) * y.w;
    ((float4*)a)[i] = x;
}

// ---------------- launch -------------------------------------------------------
extern "C" void kernel_launch(void* const* d_in, const int* in_sizes, int n_in,
                              void* d_out, int out_size) {
    const float* x    = (const float*)d_in[0];
    const float* Wq   = (const float*)d_in[1];
    const float* bq   = (const float*)d_in[2];
    const float* Wk   = (const float*)d_in[3];
    const float* bk   = (const float*)d_in[4];
    const float* Wv   = (const float*)d_in[5];
    const float* bv   = (const float*)d_in[6];
    const float* Wo   = (const float*)d_in[7];
    const float* bo   = (const float*)d_in[8];
    const float* Wg   = (const float*)d_in[9];
    const float* bg   = (const float*)d_in[10];
    const float* ln1g = (const float*)d_in[11];
    const float* ln1b = (const float*)d_in[12];
    const float* w1   = (const float*)d_in[13];
    const float* w3   = (const float*)d_in[14];
    const float* w2   = (const float*)d_in[15];
    const float* ln2g = (const float*)d_in[16];
    const float* ln2b = (const float*)d_in[17];
    const int*   sl0  = (const int*)d_in[18];
    const int*   sl1  = (const int*)d_in[19];
    float* out = (float*)d_out;

    float *xn,*qb_,*kb_,*vb_,*ob_,*gate,*x1,*xn2,*ha,*hb2,*cosb,*sinb;
    cudaGetSymbolAddress((void**)&xn,   g_xn);
    cudaGetSymbolAddress((void**)&qb_,  g_q);
    cudaGetSymbolAddress((void**)&kb_,  g_k);
    cudaGetSymbolAddress((void**)&vb_,  g_v);
    cudaGetSymbolAddress((void**)&ob_,  g_o);
    cudaGetSymbolAddress((void**)&gate, g_gate);
    cudaGetSymbolAddress((void**)&x1,   g_x1);
    cudaGetSymbolAddress((void**)&xn2,  g_xn2);
    cudaGetSymbolAddress((void**)&ha,   g_ha);
    cudaGetSymbolAddress((void**)&hb2,  g_hb);
    cudaGetSymbolAddress((void**)&cosb, g_cos);
    cudaGetSymbolAddress((void**)&sinb, g_sin);

    rope_init_kernel<<<Tn, HD>>>(cosb, sinb);
    ln_kernel<<<BT, 128>>>(x, ln1g, ln1b, xn);

    dim3 g512(D_MODEL/GBN, (BT + GBM - 1)/GBM);      // (4, 49)
    dim3 g2048(HIDDEN/GBN, (BT + GBM - 1)/GBM);      // (16, 49)

    sgemm_kernel<<<g512, 256>>>(xn, Wq, bq, nullptr, qb_, BT, D_MODEL, D_MODEL);
    sgemm_kernel<<<g512, 256>>>(xn, Wk, bk, nullptr, kb_, BT, D_MODEL, D_MODEL);
    sgemm_kernel<<<g512, 256>>>(xn, Wv, bv, nullptr, vb_, BT, D_MODEL, D_MODEL);

    rope_apply_kernel<<<dim3(Tn, Bn), 512>>>(qb_, kb_, cosb, sinb);

    attn_kernel<<<dim3((Tn + 31)/32, NHEAD, Bn), 256>>>(qb_, kb_, vb_, sl0, sl1, ob_);

    sgemm_kernel<<<g512, 256>>>(xn, Wg, bg, nullptr, gate, BT, D_MODEL, D_MODEL);
    mul_kernel<<<(BT*D_MODEL/4 + 255)/256, 256>>>(ob_, gate, BT*D_MODEL/4);
    sgemm_kernel<<<g512, 256>>>(ob_, Wo, bo, x, x1, BT, D_MODEL, D_MODEL);

    ln_kernel<<<BT, 128>>>(x1, ln2g, ln2b, xn2);
    sgemm_kernel<<<g2048, 256>>>(xn2, w1, nullptr, nullptr, ha,  BT, HIDDEN, D_MODEL);
    sgemm_kernel<<<g2048, 256>>>(xn2, w3, nullptr, nullptr, hb2, BT, HIDDEN, D_MODEL);
    silu_mul_kernel<<<(BT*HIDDEN/4 + 255)/256, 256>>>(ha, hb2, BT*HIDDEN/4);
    sgemm_kernel<<<g512, 256>>>(ha, w2, nullptr, x1, out, BT, D_MODEL, HIDDEN);
}

// round 2
// speedup vs baseline: 3.2325x; 3.2325x over previous
#include <cuda_runtime.h>
#include <math.h>
#include <stdint.h>

#define D_MODEL 512
#define NHEAD   8
#define HD      64
#define Tn      1552
#define Bn      4
#define BT      (Bn*Tn)     // 6208
#define HIDDEN  2048
#define L0c     1024
#define LTc     1536
#define CLSc    1551

// ---------------- scratch (static device arrays; no runtime alloc) -------------
__device__ float g_xn  [BT*D_MODEL];
__device__ float g_q   [BT*D_MODEL];
__device__ float g_k   [BT*D_MODEL];
__device__ float g_v   [BT*D_MODEL];
__device__ float g_o   [BT*D_MODEL];
__device__ float g_gate[BT*D_MODEL];
__device__ float g_x1  [BT*D_MODEL];
__device__ float g_xn2 [BT*D_MODEL];
__device__ float g_ha  [BT*HIDDEN];
__device__ float g_hb  [BT*HIDDEN];
__device__ float g_cos [Tn*HD];
__device__ float g_sin [Tn*HD];

// ---------------- RoPE tables --------------------------------------------------
__global__ void rope_init_kernel(float* __restrict__ c, float* __restrict__ s) {
    int t = blockIdx.x, d = threadIdx.x;   // d in [0,64)
    int i = d & 31;
    float invf = powf(10000.f, -(float)i * (1.f/32.f));
    float ph = (float)t * invf;
    c[t*HD + d] = cosf(ph);
    s[t*HD + d] = sinf(ph);
}

// ---------------- LayerNorm (row per block, 128 threads, D=512) ----------------
__global__ void ln_kernel(const float* __restrict__ x, const float* __restrict__ g,
                          const float* __restrict__ b, float* __restrict__ y) {
    int row = blockIdx.x;
    int tid = threadIdx.x;                 // 128 threads * 4 = 512
    const float4* xr = (const float4*)(x + (size_t)row*D_MODEL);
    float4 v = xr[tid];
    float s  = v.x + v.y + v.z + v.w;
    float ss = v.x*v.x + v.y*v.y + v.z*v.z + v.w*v.w;
    __shared__ float r0[4], r1[4];
    #pragma unroll
    for (int o = 16; o; o >>= 1) {
        s  += __shfl_xor_sync(0xFFFFFFFFu, s,  o);
        ss += __shfl_xor_sync(0xFFFFFFFFu, ss, o);
    }
    if ((tid & 31) == 0) { r0[tid>>5] = s; r1[tid>>5] = ss; }
    __syncthreads();
    s  = r0[0] + r0[1] + r0[2] + r0[3];
    ss = r1[0] + r1[1] + r1[2] + r1[3];
    float mu  = s  * (1.f/D_MODEL);
    float var = ss * (1.f/D_MODEL) - mu*mu;
    float inv = rsqrtf(var + 1e-5f);
    float4 gg = ((const float4*)g)[tid];
    float4 bb = ((const float4*)b)[tid];
    float4 o;
    o.x = (v.x-mu)*inv*gg.x + bb.x;
    o.y = (v.y-mu)*inv*gg.y + bb.y;
    o.z = (v.z-mu)*inv*gg.z + bb.z;
    o.w = (v.w-mu)*inv*gg.w + bb.w;
    ((float4*)(y + (size_t)row*D_MODEL))[tid] = o;
}

// ---------------- tf32 tensor-core GEMM ----------------------------------------
// C = A[M,K] @ W[K,N] (+bias) (+res). BM=BN=128, BK=16, 256 thr, 8 warps (2x4),
// warp tile 64x32 via mma.sync.m16n8k8.tf32. Double-buffered cp.async.
#define BM 128
#define BN 128
#define BK 16
#define ASTR 20     // floats; conflict-free for 8x4 fragment loads
#define BSTR 136    // floats; conflict-free for 4x8 fragment loads

__device__ __forceinline__ uint32_t f2tf(float f) {
    uint32_t r; asm("cvt.rna.tf32.f32 %0, %1;" : "=r"(r) : "f"(f)); return r;
}
__device__ __forceinline__ void cp16(uint32_t saddr, const void* gptr, int srcsz) {
    asm volatile("cp.async.cg.shared.global [%0], [%1], 16, %2;"
                 :: "r"(saddr), "l"(gptr), "r"(srcsz));
}
__device__ __forceinline__ void mma_tf32(float* c, const uint32_t* a, const uint32_t* b) {
    asm volatile("mma.sync.aligned.m16n8k8.row.col.f32.tf32.tf32.f32 "
                 "{%0,%1,%2,%3}, {%4,%5,%6,%7}, {%8,%9}, {%0,%1,%2,%3};"
                 : "+f"(c[0]), "+f"(c[1]), "+f"(c[2]), "+f"(c[3])
                 : "r"(a[0]), "r"(a[1]), "r"(a[2]), "r"(a[3]),
                   "r"(b[0]), "r"(b[1]));
}

__global__ __launch_bounds__(256)
void gemm_tf32_kernel(const float* __restrict__ A, const float* __restrict__ W,
                      const float* __restrict__ bias, const float* __restrict__ res,
                      float* __restrict__ C, int M, int N, int K) {
    __shared__ float As[2][BM*ASTR];
    __shared__ float Bs[2][BK*BSTR];

    int tid = threadIdx.x;
    int bm = blockIdx.y * BM;
    int bn = blockIdx.x * BN;
    int wid = tid >> 5, lane = tid & 31;
    int wm = wid & 1, wn = wid >> 1;        // 2 x 4 warp grid
    int gid = lane >> 2, tig = lane & 3;

    float acc[4][4][4];
    #pragma unroll
    for (int i = 0; i < 4; i++)
        #pragma unroll
        for (int j = 0; j < 4; j++)
            #pragma unroll
            for (int r = 0; r < 4; r++) acc[i][j][r] = 0.f;

    const int KT = K / BK;

    // global->shared load of one stage
    auto load_stage = [&](int kt, int stg) {
        int k0 = kt * BK;
        #pragma unroll
        for (int i = 0; i < 2; i++) {           // A: 512 float4
            int id = i * 256 + tid;
            int arow = id >> 2, ac = (id & 3) * 4;
            uint32_t sa = (uint32_t)__cvta_generic_to_shared(&As[stg][arow*ASTR + ac]);
            const float* gp = A + (size_t)(bm + arow) * K + k0 + ac;
            cp16(sa, gp, (bm + arow < M) ? 16 : 0);
        }
        #pragma unroll
        for (int i = 0; i < 2; i++) {           // B: 512 float4
            int id = i * 256 + tid;
            int brow = id >> 5, bc = (id & 31) * 4;
            uint32_t sb = (uint32_t)__cvta_generic_to_shared(&Bs[stg][brow*BSTR + bc]);
            const float* gp = W + (size_t)(k0 + brow) * N + bn + bc;
            cp16(sb, gp, 16);
        }
        asm volatile("cp.async.commit_group;");
    };

    load_stage(0, 0);

    for (int kt = 0; kt < KT; kt++) {
        int stg = kt & 1;
        if (kt + 1 < KT) {
            load_stage(kt + 1, stg ^ 1);
            asm volatile("cp.async.wait_group 1;");
        } else {
            asm volatile("cp.async.wait_group 0;");
        }
        __syncthreads();

        const float* as = As[stg];
        const float* bs = Bs[stg];
        #pragma unroll
        for (int ks = 0; ks < BK; ks += 8) {
            uint32_t af[4][4], bf[4][2];
            #pragma unroll
            for (int mi = 0; mi < 4; mi++) {
                int r = wm*64 + mi*16 + gid;
                af[mi][0] = f2tf(as[r*ASTR       + ks + tig]);
                af[mi][1] = f2tf(as[(r+8)*ASTR   + ks + tig]);
                af[mi][2] = f2tf(as[r*ASTR       + ks + 4 + tig]);
                af[mi][3] = f2tf(as[(r+8)*ASTR   + ks + 4 + tig]);
            }
            #pragma unroll
            for (int ni = 0; ni < 4; ni++) {
                int c = wn*32 + ni*8 + gid;
                bf[ni][0] = f2tf(bs[(ks + tig)*BSTR     + c]);
                bf[ni][1] = f2tf(bs[(ks + 4 + tig)*BSTR + c]);
            }
            #pragma unroll
            for (int mi = 0; mi < 4; mi++)
                #pragma unroll
                for (int ni = 0; ni < 4; ni++)
                    mma_tf32(acc[mi][ni], af[mi], bf[ni]);
        }
        __syncthreads();
    }

    // epilogue
    #pragma unroll
    for (int mi = 0; mi < 4; mi++) {
        int row0 = bm + wm*64 + mi*16 + gid;
        #pragma unroll
        for (int ni = 0; ni < 4; ni++) {
            int col = bn + wn*32 + ni*8 + tig*2;
            float b0 = bias ? bias[col]   : 0.f;
            float b1 = bias ? bias[col+1] : 0.f;
            if (row0 < M) {
                float v0 = acc[mi][ni][0] + b0;
                float v1 = acc[mi][ni][1] + b1;
                if (res) { v0 += res[(size_t)row0*N + col]; v1 += res[(size_t)row0*N + col+1]; }
                *(float2*)(C + (size_t)row0*N + col) = make_float2(v0, v1);
            }
            int row1 = row0 + 8;
            if (row1 < M) {
                float v0 = acc[mi][ni][2] + b0;
                float v1 = acc[mi][ni][3] + b1;
                if (res) { v0 += res[(size_t)row1*N + col]; v1 += res[(size_t)row1*N + col+1]; }
                *(float2*)(C + (size_t)row1*N + col) = make_float2(v0, v1);
            }
        }
    }
}

// ---------------- RoPE apply (in place, q & k) ----------------------------------
__global__ void rope_apply_kernel(float* __restrict__ q, float* __restrict__ k,
                                  const float* __restrict__ cosb,
                                  const float* __restrict__ sinb) {
    int t = blockIdx.x, b = blockIdx.y;
    int tid = threadIdx.x;                 // 512 = h*64+d
    int d = tid & 63;
    size_t base  = ((size_t)b*Tn + t)*D_MODEL + tid;
    size_t pbase = ((size_t)b*Tn + t)*D_MODEL + (tid & ~63) + ((d < 32) ? d + 32 : d - 32);
    float c = cosb[t*HD + d], s = sinb[t*HD + d];
    float qv = q[base],  kv = k[base];
    float qp = q[pbase], kp = k[pbase];
    float sg = (d < 32) ? -1.f : 1.f;
    __syncthreads();                       // all partner reads done before writes
    q[base] = qv*c + sg*qp*s;
    k[base] = kv*c + sg*kp*s;
}

// ---------------- mask predicate ------------------------------------------------
__device__ __forceinline__ bool allowed_fn(int qi, int j, int s0, int s1) {
    int qd = (qi < L0c) ? 0 : (qi < LTc ? 1 : (qi < CLSc ? 2 : 3));
    if (j < L0c)       return (j < s0)          && ((qd == 0 && j <= qi) || qd >= 2);
    else if (j < LTc)  return ((j - L0c) < s1)  && ((qd == 1 && j <= qi) || qd >= 2);
    else if (j < CLSc) return true;            // NS keys reachable by everyone
    else               return qd == 3;         // only CLS attends CLS
}

// ---------------- attention: BQ=32 rows, 32-key chunks, online softmax ----------
__global__ __launch_bounds__(256)
void attn_kernel(const float* __restrict__ q, const float* __restrict__ k,
                 const float* __restrict__ v,
                 const int* __restrict__ sl0p, const int* __restrict__ sl1p,
                 float* __restrict__ o) {
    int qb = blockIdx.x, h = blockIdx.y, b = blockIdx.z;
    int tid = threadIdx.x;                 // 256
    __shared__ float qs[32][68];
    __shared__ float ks[32][68];
    __shared__ float vs[32][68];
    __shared__ float ps[32][33];
    const int s0 = sl0p[b], s1 = sl1p[b];
    const size_t hb = (size_t)b * Tn * D_MODEL + (size_t)h * HD;
    int q0 = qb * 32;
    int qmax = q0 + 31;
    int qd = (q0 < L0c) ? 0 : (q0 < LTc ? 1 : 2);   // tiles never straddle 1024/1536

    {   // load Q tile (2048 floats, 8 per thread)
        int r = tid >> 3, c4 = (tid & 7) * 8;
        int qi = q0 + r;
        float4 z = make_float4(0.f,0.f,0.f,0.f);
        if (qi < Tn) {
            const float4* src = (const float4*)(q + hb + (size_t)qi*D_MODEL + c4);
            *(float4*)&qs[r][c4]     = src[0];
            *(float4*)&qs[r][c4 + 4] = src[1];
        } else {
            *(float4*)&qs[r][c4]     = z;
            *(float4*)&qs[r][c4 + 4] = z;
        }
    }

    int row = tid >> 3;                    // 0..31 (query row within tile)
    int kc  = tid & 7;                     // key sub-column
    int dg  = (tid & 7) * 8;               // d-slice for accumulation
    int myq = q0 + row;
    float m_run = -1e30f, l_run = 0.f;
    float acc[8];
    #pragma unroll
    for (int i = 0; i < 8; i++) acc[i] = 0.f;

    for (int c0 = 0; c0 < Tn; c0 += 32) {
        // conservative tile-level skip of fully-masked chunks (uniform per block)
        bool keep;
        if (c0 >= LTc) {
            keep = true;                                    // NS/CLS keys
        } else if (c0 < L0c) {
            keep = (qd == 0) ? (c0 <= qmax && c0 < s0)
                 : (qd == 2) ? (c0 < s0) : false;
        } else {
            keep = (qd == 1) ? (c0 <= qmax && (c0 - L0c) < s1)
                 : (qd == 2) ? ((c0 - L0c) < s1) : false;
        }
        if (!keep) continue;

        {   // stage K,V chunk
            int r = tid >> 3, c4 = (tid & 7) * 8;
            int j = c0 + r;
            float4 z = make_float4(0.f,0.f,0.f,0.f);
            if (j < Tn) {
                const float4* ksrc = (const float4*)(k + hb + (size_t)j*D_MODEL + c4);
                const float4* vsrc = (const float4*)(v + hb + (size_t)j*D_MODEL + c4);
                *(float4*)&ks[r][c4]     = ksrc[0];
                *(float4*)&ks[r][c4 + 4] = ksrc[1];
                *(float4*)&vs[r][c4]     = vsrc[0];
                *(float4*)&vs[r][c4 + 4] = vsrc[1];
            } else {
                *(float4*)&ks[r][c4] = z; *(float4*)&ks[r][c4+4] = z;
                *(float4*)&vs[r][c4] = z; *(float4*)&vs[r][c4+4] = z;
            }
        }
        __syncthreads();

        // scores: this thread handles keys jj = kc + u*8, u=0..3
        float dot[4] = {0.f, 0.f, 0.f, 0.f};
        #pragma unroll
        for (int i2 = 0; i2 < 16; i2++) {
            float4 qv = *(const float4*)&qs[row][i2*4];
            #pragma unroll
            for (int u = 0; u < 4; u++) {
                float4 kv = *(const float4*)&ks[kc + u*8][i2*4];
                dot[u] += qv.x*kv.x + qv.y*kv.y + qv.z*kv.z + qv.w*kv.w;
            }
        }
        float sreg[4];
        #pragma unroll
        for (int u = 0; u < 4; u++) {
            int j = c0 + kc + u*8;
            bool ok = (j < Tn) && (myq < Tn) && allowed_fn(myq, j, s0, s1);
            sreg[u] = ok ? dot[u] * 0.125f : -1e9f;
        }
        // per-row reduce over the 8 lanes of this row (lanes differ only in kc)
        float cmax = fmaxf(fmaxf(sreg[0], sreg[1]), fmaxf(sreg[2], sreg[3]));
        #pragma unroll
        for (int ofs = 4; ofs; ofs >>= 1)
            cmax = fmaxf(cmax, __shfl_xor_sync(0xFFFFFFFFu, cmax, ofs));
        float m_new = fmaxf(m_run, cmax);
        float scale = __expf(m_run - m_new);
        float csum = 0.f;
        #pragma unroll
        for (int u = 0; u < 4; u++) {
            float p = __expf(sreg[u] - m_new);
            csum += p;
            ps[row][kc + u*8] = p;
        }
        #pragma unroll
        for (int ofs = 4; ofs; ofs >>= 1)
            csum += __shfl_xor_sync(0xFFFFFFFFu, csum, ofs);
        l_run = l_run * scale + csum;
        m_run = m_new;
        __syncwarp();                      // ps produced/consumed within the warp

        #pragma unroll
        for (int i = 0; i < 8; i++) acc[i] *= scale;
        for (int jj = 0; jj < 32; jj++) {
            float p = ps[row][jj];
            float4 v0 = *(const float4*)&vs[jj][dg];
            float4 v1 = *(const float4*)&vs[jj][dg + 4];
            acc[0] += p*v0.x; acc[1] += p*v0.y; acc[2] += p*v0.z; acc[3] += p*v0.w;
            acc[4] += p*v1.x; acc[5] += p*v1.y; acc[6] += p*v1.z; acc[7] += p*v1.w;
        }
        __syncthreads();                   // protect ks/vs before next stage
    }

    if (myq < Tn) {
        float inv = 1.f / l_run;
        float* dst = o + hb + (size_t)myq*D_MODEL + dg;
        float4 o0 = make_float4(acc[0]*inv, acc[1]*inv, acc[2]*inv, acc[3]*inv);
        float4 o1 = make_float4(acc[4]*inv, acc[5]*inv, acc[6]*inv, acc[7]*inv);
        *(float4*)(dst)     = o0;
        *(float4*)(dst + 4) = o1;
    }
}

// ---------------- elementwise --------------------------------------------------
__global__ void mul_kernel(float* __restrict__ a, const float* __restrict__ b, int n4) {
    int i = blockIdx.x*blockDim.x + threadIdx.x;
    if (i >= n4) return;
    float4 x = ((const float4*)a)[i]; float4 y = ((const float4*)b)[i];
    x.x *= y.x; x.y *= y.y; x.z *= y.z; x.w *= y.w;
    ((float4*)a)[i] = x;
}
__global__ void silu_mul_kernel(float* __restrict__ a, const float* __restrict__ b, int n4) {
    int i = blockIdx.x*blockDim.x + threadIdx.x;
    if (i >= n4) return;
    float4 x = ((const float4*)a)[i]; float4 y = ((const float4*)b)[i];
    x.x = x.x / (1.f + __expf(-x.x)) * y.x;
    x.y = x.y / (1.f + __expf(-x.y)) * y.y;
    x.z = x.z / (1.f + __expf(-x.z)) * y.z;
    x.w = x.w / (1.f + __expf(-x.w)) * y.w;
    ((float4*)a)[i] = x;
}

// ---------------- launch -------------------------------------------------------
extern "C" void kernel_launch(void* const* d_in, const int* in_sizes, int n_in,
                              void* d_out, int out_size) {
    const float* x    = (const float*)d_in[0];
    const float* Wq   = (const float*)d_in[1];
    const float* bq   = (const float*)d_in[2];
    const float* Wk   = (const float*)d_in[3];
    const float* bk   = (const float*)d_in[4];
    const float* Wv   = (const float*)d_in[5];
    const float* bv   = (const float*)d_in[6];
    const float* Wo   = (const float*)d_in[7];
    const float* bo   = (const float*)d_in[8];
    const float* Wg   = (const float*)d_in[9];
    const float* bg   = (const float*)d_in[10];
    const float* ln1g = (const float*)d_in[11];
    const float* ln1b = (const float*)d_in[12];
    const float* w1   = (const float*)d_in[13];
    const float* w3   = (const float*)d_in[14];
    const float* w2   = (const float*)d_in[15];
    const float* ln2g = (const float*)d_in[16];
    const float* ln2b = (const float*)d_in[17];
    const int*   sl0  = (const int*)d_in[18];
    const int*   sl1  = (const int*)d_in[19];
    float* out = (float*)d_out;

    float *xn,*qb_,*kb_,*vb_,*ob_,*gate,*x1,*xn2,*ha,*hb2,*cosb,*sinb;
    cudaGetSymbolAddress((void**)&xn,   g_xn);
    cudaGetSymbolAddress((void**)&qb_,  g_q);
    cudaGetSymbolAddress((void**)&kb_,  g_k);
    cudaGetSymbolAddress((void**)&vb_,  g_v);
    cudaGetSymbolAddress((void**)&ob_,  g_o);
    cudaGetSymbolAddress((void**)&gate, g_gate);
    cudaGetSymbolAddress((void**)&x1,   g_x1);
    cudaGetSymbolAddress((void**)&xn2,  g_xn2);
    cudaGetSymbolAddress((void**)&ha,   g_ha);
    cudaGetSymbolAddress((void**)&hb2,  g_hb);
    cudaGetSymbolAddress((void**)&cosb, g_cos);
    cudaGetSymbolAddress((void**)&sinb, g_sin);

    rope_init_kernel<<<Tn, HD>>>(cosb, sinb);
    ln_kernel<<<BT, 128>>>(x, ln1g, ln1b, xn);

    dim3 g512(D_MODEL/BN, (BT + BM - 1)/BM);       // (4, 49)
    dim3 g2048(HIDDEN/BN, (BT + BM - 1)/BM);       // (16, 49)

    gemm_tf32_kernel<<<g512, 256>>>(xn, Wq, bq, nullptr, qb_, BT, D_MODEL, D_MODEL);
    gemm_tf32_kernel<<<g512, 256>>>(xn, Wk, bk, nullptr, kb_, BT, D_MODEL, D_MODEL);
    gemm_tf32_kernel<<<g512, 256>>>(xn, Wv, bv, nullptr, vb_, BT, D_MODEL, D_MODEL);

    rope_apply_kernel<<<dim3(Tn, Bn), 512>>>(qb_, kb_, cosb, sinb);

    attn_kernel<<<dim3((Tn + 31)/32, NHEAD, Bn), 256>>>(qb_, kb_, vb_, sl0, sl1, ob_);

    gemm_tf32_kernel<<<g512, 256>>>(xn, Wg, bg, nullptr, gate, BT, D_MODEL, D_MODEL);
    mul_kernel<<<(BT*D_MODEL/4 + 255)/256, 256>>>(ob_, gate, BT*D_MODEL/4);
    gemm_tf32_kernel<<<g512, 256>>>(ob_, Wo, bo, x, x1, BT, D_MODEL, D_MODEL);

    ln_kernel<<<BT, 128>>>(x1, ln2g, ln2b, xn2);
    gemm_tf32_kernel<<<g2048, 256>>>(xn2, w1, nullptr, nullptr, ha,  BT, HIDDEN, D_MODEL);
    gemm_tf32_kernel<<<g2048, 256>>>(xn2, w3, nullptr, nullptr, hb2, BT, HIDDEN, D_MODEL);
    silu_mul_kernel<<<(BT*HIDDEN/4 + 255)/256, 256>>>(ha, hb2, BT*HIDDEN/4);
    gemm_tf32_kernel<<<g512, 256>>>(ha, w2, nullptr, x1, out, BT, D_MODEL, HIDDEN);
}

// round 3
// speedup vs baseline: 3.4212x; 1.0584x over previous
#include <cuda_runtime.h>
#include <math.h>
#include <stdint.h>

#define D_MODEL 512
#define NHEAD   8
#define HD      64
#define Tn      1552
#define Bn      4
#define BT      (Bn*Tn)     // 6208
#define HIDDEN  2048
#define L0c     1024
#define LTc     1536
#define CLSc    1551

// ---------------- scratch (static device arrays; no runtime alloc) -------------
__device__ float g_xn  [BT*D_MODEL];
__device__ float g_q   [BT*D_MODEL];
__device__ float g_k   [BT*D_MODEL];
__device__ float g_v   [BT*D_MODEL];
__device__ float g_o   [BT*D_MODEL];
__device__ float g_gate[BT*D_MODEL];
__device__ float g_x1  [BT*D_MODEL];
__device__ float g_xn2 [BT*D_MODEL];
__device__ float g_ha  [BT*HIDDEN];
__device__ float g_hb  [BT*HIDDEN];
__device__ float g_cos [Tn*HD];
__device__ float g_sin [Tn*HD];

// ---------------- RoPE tables --------------------------------------------------
__global__ void rope_init_kernel(float* __restrict__ c, float* __restrict__ s) {
    int t = blockIdx.x, d = threadIdx.x;   // d in [0,64)
    int i = d & 31;
    float invf = powf(10000.f, -(float)i * (1.f/32.f));
    float ph = (float)t * invf;
    c[t*HD + d] = cosf(ph);
    s[t*HD + d] = sinf(ph);
}

// ---------------- LayerNorm (row per block, 128 threads, D=512) ----------------
__global__ void ln_kernel(const float* __restrict__ x, const float* __restrict__ g,
                          const float* __restrict__ b, float* __restrict__ y) {
    int row = blockIdx.x;
    int tid = threadIdx.x;                 // 128 threads * 4 = 512
    const float4* xr = (const float4*)(x + (size_t)row*D_MODEL);
    float4 v = xr[tid];
    float s  = v.x + v.y + v.z + v.w;
    float ss = v.x*v.x + v.y*v.y + v.z*v.z + v.w*v.w;
    __shared__ float r0[4], r1[4];
    #pragma unroll
    for (int o = 16; o; o >>= 1) {
        s  += __shfl_xor_sync(0xFFFFFFFFu, s,  o);
        ss += __shfl_xor_sync(0xFFFFFFFFu, ss, o);
    }
    if ((tid & 31) == 0) { r0[tid>>5] = s; r1[tid>>5] = ss; }
    __syncthreads();
    s  = r0[0] + r0[1] + r0[2] + r0[3];
    ss = r1[0] + r1[1] + r1[2] + r1[3];
    float mu  = s  * (1.f/D_MODEL);
    float var = ss * (1.f/D_MODEL) - mu*mu;
    float inv = rsqrtf(var + 1e-5f);
    float4 gg = ((const float4*)g)[tid];
    float4 bb = ((const float4*)b)[tid];
    float4 o;
    o.x = (v.x-mu)*inv*gg.x + bb.x;
    o.y = (v.y-mu)*inv*gg.y + bb.y;
    o.z = (v.z-mu)*inv*gg.z + bb.z;
    o.w = (v.w-mu)*inv*gg.w + bb.w;
    ((float4*)(y + (size_t)row*D_MODEL))[tid] = o;
}

// ---------------- tf32 tensor-core GEMM (templated N-tile, multi-weight) -------
// C = A[M,K] @ W[K,Nw] (+bias) (+res). Up to 4 weights fused along N
// (block column selects the weight). BM=128, BK=16, 256 thr.
#define BM 128
#define BK 16
#define ASTR 20     // floats; conflict-free for fragment loads

__device__ __forceinline__ uint32_t f2tf(float f) {
    uint32_t r; asm("cvt.rna.tf32.f32 %0, %1;" : "=r"(r) : "f"(f)); return r;
}
__device__ __forceinline__ void cp16(uint32_t saddr, const void* gptr, int srcsz) {
    asm volatile("cp.async.cg.shared.global [%0], [%1], 16, %2;"
                 :: "r"(saddr), "l"(gptr), "r"(srcsz));
}
__device__ __forceinline__ void mma_tf32(float* c, const uint32_t* a, const uint32_t* b) {
    asm volatile("mma.sync.aligned.m16n8k8.row.col.f32.tf32.tf32.f32 "
                 "{%0,%1,%2,%3}, {%4,%5,%6,%7}, {%8,%9}, {%0,%1,%2,%3};"
                 : "+f"(c[0]), "+f"(c[1]), "+f"(c[2]), "+f"(c[3])
                 : "r"(a[0]), "r"(a[1]), "r"(a[2]), "r"(a[3]),
                   "r"(b[0]), "r"(b[1]));
}

template<int BNt>
__global__ __launch_bounds__(256)
void gemm_tc(const float* __restrict__ A,
             const float* W0, const float* W1, const float* W2, const float* W3,
             const float* b0, const float* b1, const float* b2, const float* b3,
             const float* __restrict__ res,
             float* C0, float* C1, float* C2, float* C3,
             int M, int Nw, int K) {
    constexpr int BSTRt = BNt + 8;
    constexpr int WR = (BNt == 128) ? 2 : 4;        // warp rows
    constexpr int WC = 8 / WR;                      // warp cols
    constexpr int MI = BM / WR / 16;                // m16 frags per warp
    constexpr int NI = BNt / WC / 8;                // n8 frags per warp
    constexpr int LB = (BK * BNt / 4) / 256;        // B float4 loads per thread

    __shared__ float As[2][BM*ASTR];
    __shared__ float Bs[2][BK*BSTRt];

    int tid = threadIdx.x;
    int bm = blockIdx.y * BM;
    int gcol0 = blockIdx.x * BNt;
    int widx = gcol0 / Nw;
    int bn = gcol0 - widx * Nw;
    const float* W    = (widx==0) ? W0 : (widx==1) ? W1 : (widx==2) ? W2 : W3;
    const float* bias = (widx==0) ? b0 : (widx==1) ? b1 : (widx==2) ? b2 : b3;
    float*       C    = (widx==0) ? C0 : (widx==1) ? C1 : (widx==2) ? C2 : C3;

    int wid = tid >> 5, lane = tid & 31;
    int wm = wid % WR, wn = wid / WR;
    int gid = lane >> 2, tig = lane & 3;

    float acc[MI][NI][4];
    #pragma unroll
    for (int i = 0; i < MI; i++)
        #pragma unroll
        for (int j = 0; j < NI; j++)
            #pragma unroll
            for (int r = 0; r < 4; r++) acc[i][j][r] = 0.f;

    const int KT = K / BK;

    auto load_stage = [&](int kt, int stg) {
        int k0 = kt * BK;
        #pragma unroll
        for (int i = 0; i < 2; i++) {           // A: 512 float4
            int id = i * 256 + tid;
            int arow = id >> 2, ac = (id & 3) * 4;
            uint32_t sa = (uint32_t)__cvta_generic_to_shared(&As[stg][arow*ASTR + ac]);
            const float* gp = A + (size_t)(bm + arow) * K + k0 + ac;
            cp16(sa, gp, (bm + arow < M) ? 16 : 0);
        }
        #pragma unroll
        for (int i = 0; i < LB; i++) {          // B
            int id = i * 256 + tid;
            int brow = id / (BNt/4), bc = (id % (BNt/4)) * 4;
            uint32_t sb = (uint32_t)__cvta_generic_to_shared(&Bs[stg][brow*BSTRt + bc]);
            const float* gp = W + (size_t)(k0 + brow) * Nw + bn + bc;
            cp16(sb, gp, 16);
        }
        asm volatile("cp.async.commit_group;");
    };

    load_stage(0, 0);

    for (int kt = 0; kt < KT; kt++) {
        int stg = kt & 1;
        if (kt + 1 < KT) {
            load_stage(kt + 1, stg ^ 1);
            asm volatile("cp.async.wait_group 1;");
        } else {
            asm volatile("cp.async.wait_group 0;");
        }
        __syncthreads();

        const float* as = As[stg];
        const float* bs = Bs[stg];
        #pragma unroll
        for (int ks = 0; ks < BK; ks += 8) {
            uint32_t af[MI][4], bf[NI][2];
            #pragma unroll
            for (int mi = 0; mi < MI; mi++) {
                int r = wm*(BM/WR) + mi*16 + gid;
                af[mi][0] = f2tf(as[r*ASTR       + ks + tig]);
                af[mi][1] = f2tf(as[(r+8)*ASTR   + ks + tig]);
                af[mi][2] = f2tf(as[r*ASTR       + ks + 4 + tig]);
                af[mi][3] = f2tf(as[(r+8)*ASTR   + ks + 4 + tig]);
            }
            #pragma unroll
            for (int ni = 0; ni < NI; ni++) {
                int c = wn*(BNt/WC) + ni*8 + gid;
                bf[ni][0] = f2tf(bs[(ks + tig)*BSTRt     + c]);
                bf[ni][1] = f2tf(bs[(ks + 4 + tig)*BSTRt + c]);
            }
            #pragma unroll
            for (int mi = 0; mi < MI; mi++)
                #pragma unroll
                for (int ni = 0; ni < NI; ni++)
                    mma_tf32(acc[mi][ni], af[mi], bf[ni]);
        }
        __syncthreads();
    }

    // epilogue
    #pragma unroll
    for (int mi = 0; mi < MI; mi++) {
        int row0 = bm + wm*(BM/WR) + mi*16 + gid;
        #pragma unroll
        for (int ni = 0; ni < NI; ni++) {
            int col = bn + wn*(BNt/WC) + ni*8 + tig*2;
            float bb0 = bias ? bias[col]   : 0.f;
            float bb1 = bias ? bias[col+1] : 0.f;
            if (row0 < M) {
                float v0 = acc[mi][ni][0] + bb0;
                float v1 = acc[mi][ni][1] + bb1;
                if (res) { v0 += res[(size_t)row0*Nw + col]; v1 += res[(size_t)row0*Nw + col+1]; }
                *(float2*)(C + (size_t)row0*Nw + col) = make_float2(v0, v1);
            }
            int row1 = row0 + 8;
            if (row1 < M) {
                float v0 = acc[mi][ni][2] + bb0;
                float v1 = acc[mi][ni][3] + bb1;
                if (res) { v0 += res[(size_t)row1*Nw + col]; v1 += res[(size_t)row1*Nw + col+1]; }
                *(float2*)(C + (size_t)row1*Nw + col) = make_float2(v0, v1);
            }
        }
    }
}

// ---------------- RoPE apply (in place, q & k) ----------------------------------
__global__ void rope_apply_kernel(float* __restrict__ q, float* __restrict__ k,
                                  const float* __restrict__ cosb,
                                  const float* __restrict__ sinb) {
    int t = blockIdx.x, b = blockIdx.y;
    int tid = threadIdx.x;                 // 512 = h*64+d
    int d = tid & 63;
    size_t base  = ((size_t)b*Tn + t)*D_MODEL + tid;
    size_t pbase = ((size_t)b*Tn + t)*D_MODEL + (tid & ~63) + ((d < 32) ? d + 32 : d - 32);
    float c = cosb[t*HD + d], s = sinb[t*HD + d];
    float qv = q[base],  kv = k[base];
    float qp = q[pbase], kp = k[pbase];
    float sg = (d < 32) ? -1.f : 1.f;
    __syncthreads();                       // all partner reads done before writes
    q[base] = qv*c + sg*qp*s;
    k[base] = kv*c + sg*kp*s;
}

// ---------------- mask predicate ------------------------------------------------
__device__ __forceinline__ bool allowed_fn(int qi, int j, int s0, int s1) {
    int qd = (qi < L0c) ? 0 : (qi < LTc ? 1 : (qi < CLSc ? 2 : 3));
    if (j < L0c)       return (j < s0)          && ((qd == 0 && j <= qi) || qd >= 2);
    else if (j < LTc)  return ((j - L0c) < s1)  && ((qd == 1 && j <= qi) || qd >= 2);
    else if (j < CLSc) return true;
    else               return qd == 3;
}

// ---------------- attention (gate fused into epilogue) --------------------------
__global__ __launch_bounds__(256)
void attn_kernel(const float* __restrict__ q, const float* __restrict__ k,
                 const float* __restrict__ v, const float* __restrict__ gate,
                 const int* __restrict__ sl0p, const int* __restrict__ sl1p,
                 float* __restrict__ o) {
    int qb = blockIdx.x, h = blockIdx.y, b = blockIdx.z;
    int tid = threadIdx.x;                 // 256
    __shared__ float qs[32][68];
    __shared__ float ks[32][68];
    __shared__ float vs[32][68];
    __shared__ float ps[32][33];
    const int s0 = sl0p[b], s1 = sl1p[b];
    const size_t hb = (size_t)b * Tn * D_MODEL + (size_t)h * HD;
    int q0 = qb * 32;
    int qmax = q0 + 31;
    int qd = (q0 < L0c) ? 0 : (q0 < LTc ? 1 : 2);   // tiles never straddle 1024/1536

    {   // load Q tile
        int r = tid >> 3, c4 = (tid & 7) * 8;
        int qi = q0 + r;
        float4 z = make_float4(0.f,0.f,0.f,0.f);
        if (qi < Tn) {
            const float4* src = (const float4*)(q + hb + (size_t)qi*D_MODEL + c4);
            *(float4*)&qs[r][c4]     = src[0];
            *(float4*)&qs[r][c4 + 4] = src[1];
        } else {
            *(float4*)&qs[r][c4]     = z;
            *(float4*)&qs[r][c4 + 4] = z;
        }
    }

    int row = tid >> 3;
    int kc  = tid & 7;
    int dg  = (tid & 7) * 8;
    int myq = q0 + row;
    float m_run = -1e30f, l_run = 0.f;
    float acc[8];
    #pragma unroll
    for (int i = 0; i < 8; i++) acc[i] = 0.f;

    for (int c0 = 0; c0 < Tn; c0 += 32) {
        bool keep;
        if (c0 >= LTc) {
            keep = true;
        } else if (c0 < L0c) {
            keep = (qd == 0) ? (c0 <= qmax && c0 < s0)
                 : (qd == 2) ? (c0 < s0) : false;
        } else {
            keep = (qd == 1) ? (c0 <= qmax && (c0 - L0c) < s1)
                 : (qd == 2) ? ((c0 - L0c) < s1) : false;
        }
        if (!keep) continue;

        {   // stage K,V chunk
            int r = tid >> 3, c4 = (tid & 7) * 8;
            int j = c0 + r;
            float4 z = make_float4(0.f,0.f,0.f,0.f);
            if (j < Tn) {
                const float4* ksrc = (const float4*)(k + hb + (size_t)j*D_MODEL + c4);
                const float4* vsrc = (const float4*)(v + hb + (size_t)j*D_MODEL + c4);
                *(float4*)&ks[r][c4]     = ksrc[0];
                *(float4*)&ks[r][c4 + 4] = ksrc[1];
                *(float4*)&vs[r][c4]     = vsrc[0];
                *(float4*)&vs[r][c4 + 4] = vsrc[1];
            } else {
                *(float4*)&ks[r][c4] = z; *(float4*)&ks[r][c4+4] = z;
                *(float4*)&vs[r][c4] = z; *(float4*)&vs[r][c4+4] = z;
            }
        }
        __syncthreads();

        float dot[4] = {0.f, 0.f, 0.f, 0.f};
        #pragma unroll
        for (int i2 = 0; i2 < 16; i2++) {
            float4 qv = *(const float4*)&qs[row][i2*4];
            #pragma unroll
            for (int u = 0; u < 4; u++) {
                float4 kv = *(const float4*)&ks[kc + u*8][i2*4];
                dot[u] += qv.x*kv.x + qv.y*kv.y + qv.z*kv.z + qv.w*kv.w;
            }
        }
        float sreg[4];
        #pragma unroll
        for (int u = 0; u < 4; u++) {
            int j = c0 + kc + u*8;
            bool ok = (j < Tn) && (myq < Tn) && allowed_fn(myq, j, s0, s1);
            sreg[u] = ok ? dot[u] * 0.125f : -1e9f;
        }
        float cmax = fmaxf(fmaxf(sreg[0], sreg[1]), fmaxf(sreg[2], sreg[3]));
        #pragma unroll
        for (int ofs = 4; ofs; ofs >>= 1)
            cmax = fmaxf(cmax, __shfl_xor_sync(0xFFFFFFFFu, cmax, ofs));
        float m_new = fmaxf(m_run, cmax);
        float scale = __expf(m_run - m_new);
        float csum = 0.f;
        #pragma unroll
        for (int u = 0; u < 4; u++) {
            float p = __expf(sreg[u] - m_new);
            csum += p;
            ps[row][kc + u*8] = p;
        }
        #pragma unroll
        for (int ofs = 4; ofs; ofs >>= 1)
            csum += __shfl_xor_sync(0xFFFFFFFFu, csum, ofs);
        l_run = l_run * scale + csum;
        m_run = m_new;
        __syncwarp();

        #pragma unroll
        for (int i = 0; i < 8; i++) acc[i] *= scale;
        for (int jj = 0; jj < 32; jj++) {
            float p = ps[row][jj];
            float4 v0 = *(const float4*)&vs[jj][dg];
            float4 v1 = *(const float4*)&vs[jj][dg + 4];
            acc[0] += p*v0.x; acc[1] += p*v0.y; acc[2] += p*v0.z; acc[3] += p*v0.w;
            acc[4] += p*v1.x; acc[5] += p*v1.y; acc[6] += p*v1.z; acc[7] += p*v1.w;
        }
        __syncthreads();
    }

    if (myq < Tn) {
        float inv = 1.f / l_run;
        size_t off = hb + (size_t)myq*D_MODEL + dg;
        float4 ga = *(const float4*)(gate + off);
        float4 gb = *(const float4*)(gate + off + 4);
        float4 o0 = make_float4(acc[0]*inv*ga.x, acc[1]*inv*ga.y,
                                acc[2]*inv*ga.z, acc[3]*inv*ga.w);
        float4 o1 = make_float4(acc[4]*inv*gb.x, acc[5]*inv*gb.y,
                                acc[6]*inv*gb.z, acc[7]*inv*gb.w);
        *(float4*)(o + off)     = o0;
        *(float4*)(o + off + 4) = o1;
    }
}

// ---------------- elementwise --------------------------------------------------
__global__ void silu_mul_kernel(float* __restrict__ a, const float* __restrict__ b, int n4) {
    int i = blockIdx.x*blockDim.x + threadIdx.x;
    if (i >= n4) return;
    float4 x = ((const float4*)a)[i]; float4 y = ((const float4*)b)[i];
    x.x = x.x / (1.f + __expf(-x.x)) * y.x;
    x.y = x.y / (1.f + __expf(-x.y)) * y.y;
    x.z = x.z / (1.f + __expf(-x.z)) * y.z;
    x.w = x.w / (1.f + __expf(-x.w)) * y.w;
    ((float4*)a)[i] = x;
}

// ---------------- launch -------------------------------------------------------
extern "C" void kernel_launch(void* const* d_in, const int* in_sizes, int n_in,
                              void* d_out, int out_size) {
    const float* x    = (const float*)d_in[0];
    const float* Wq   = (const float*)d_in[1];
    const float* bq   = (const float*)d_in[2];
    const float* Wk   = (const float*)d_in[3];
    const float* bk   = (const float*)d_in[4];
    const float* Wv   = (const float*)d_in[5];
    const float* bv   = (const float*)d_in[6];
    const float* Wo   = (const float*)d_in[7];
    const float* bo   = (const float*)d_in[8];
    const float* Wg   = (const float*)d_in[9];
    const float* bg   = (const float*)d_in[10];
    const float* ln1g = (const float*)d_in[11];
    const float* ln1b = (const float*)d_in[12];
    const float* w1   = (const float*)d_in[13];
    const float* w3   = (const float*)d_in[14];
    const float* w2   = (const float*)d_in[15];
    const float* ln2g = (const float*)d_in[16];
    const float* ln2b = (const float*)d_in[17];
    const int*   sl0  = (const int*)d_in[18];
    const int*   sl1  = (const int*)d_in[19];
    float* out = (float*)d_out;

    float *xn,*qb_,*kb_,*vb_,*ob_,*gate,*x1,*xn2,*ha,*hb2,*cosb,*sinb;
    cudaGetSymbolAddress((void**)&xn,   g_xn);
    cudaGetSymbolAddress((void**)&qb_,  g_q);
    cudaGetSymbolAddress((void**)&kb_,  g_k);
    cudaGetSymbolAddress((void**)&vb_,  g_v);
    cudaGetSymbolAddress((void**)&ob_,  g_o);
    cudaGetSymbolAddress((void**)&gate, g_gate);
    cudaGetSymbolAddress((void**)&x1,   g_x1);
    cudaGetSymbolAddress((void**)&xn2,  g_xn2);
    cudaGetSymbolAddress((void**)&ha,   g_ha);
    cudaGetSymbolAddress((void**)&hb2,  g_hb);
    cudaGetSymbolAddress((void**)&cosb, g_cos);
    cudaGetSymbolAddress((void**)&sinb, g_sin);

    rope_init_kernel<<<Tn, HD>>>(cosb, sinb);
    ln_kernel<<<BT, 128>>>(x, ln1g, ln1b, xn);

    const int MB = (BT + BM - 1) / BM;             // 49

    // fused Q,K,V,gate GEMM: effective N = 4*512 = 2048, grid (16, 49)
    gemm_tc<128><<<dim3(4*D_MODEL/128, MB), 256>>>(
        xn, Wq, Wk, Wv, Wg, bq, bk, bv, bg, nullptr,
        qb_, kb_, vb_, gate, BT, D_MODEL, D_MODEL);

    rope_apply_kernel<<<dim3(Tn, Bn), 512>>>(qb_, kb_, cosb, sinb);

    attn_kernel<<<dim3((Tn + 31)/32, NHEAD, Bn), 256>>>(qb_, kb_, vb_, gate, sl0, sl1, ob_);

    // Wo GEMM: BN=64 for better wave balance, grid (8, 49)
    gemm_tc<64><<<dim3(D_MODEL/64, MB), 256>>>(
        ob_, Wo, Wo, Wo, Wo, bo, bo, bo, bo, x,
        x1, x1, x1, x1, BT, D_MODEL, D_MODEL);

    ln_kernel<<<BT, 128>>>(x1, ln2g, ln2b, xn2);

    // fused w1,w3 GEMM: effective N = 2*2048 = 4096, grid (32, 49)
    gemm_tc<128><<<dim3(2*HIDDEN/128, MB), 256>>>(
        xn2, w1, w3, w1, w3, nullptr, nullptr, nullptr, nullptr, nullptr,
        ha, hb2, ha, hb2, BT, HIDDEN, D_MODEL);

    silu_mul_kernel<<<(BT*HIDDEN/4 + 255)/256, 256>>>(ha, hb2, BT*HIDDEN/4);

    // w2 GEMM: K=2048, BN=64, grid (8, 49)
    gemm_tc<64><<<dim3(D_MODEL/64, MB), 256>>>(
        ha, w2, w2, w2, w2, nullptr, nullptr, nullptr, nullptr, x1,
        out, out, out, out, BT, D_MODEL, HIDDEN);
}

// round 4
// speedup vs baseline: 4.2147x; 1.2319x over previous
#include <cuda_runtime.h>
#include <cuda_bf16.h>
#include <math.h>
#include <stdint.h>

#define D_MODEL 512
#define NHEAD   8
#define HD      64
#define Tn      1552
#define Bn      4
#define BT      (Bn*Tn)     // 6208
#define HIDDEN  2048
#define L0c     1024
#define LTc     1536
#define CLSc    1551

// weight bf16 buffer offsets (in elements)
#define WOFF_Q  0
#define WOFF_K  262144
#define WOFF_V  524288
#define WOFF_G  786432
#define WOFF_O  1048576
#define WOFF_1  1310720
#define WOFF_3  2359296
#define WOFF_2  3407872
#define WTOT    4456448

// ---------------- scratch (static device arrays; no runtime alloc) -------------
__device__ __nv_bfloat16 g_wbf [WTOT];          // all weights, bf16
__device__ __nv_bfloat16 g_xnb [BT*D_MODEL];    // ln1 out (bf16, GEMM A)
__device__ __nv_bfloat16 g_xn2b[BT*D_MODEL];    // ln2 out (bf16)
__device__ __nv_bfloat16 g_obb [BT*D_MODEL];    // gated attn out (bf16)
__device__ __nv_bfloat16 g_hab [BT*HIDDEN];     // silu(ha)*hb (bf16)
__device__ float g_q   [BT*D_MODEL];
__device__ float g_k   [BT*D_MODEL];
__device__ float g_v   [BT*D_MODEL];
__device__ float g_gate[BT*D_MODEL];
__device__ float g_x1  [BT*D_MODEL];
__device__ float g_ha  [BT*HIDDEN];
__device__ float g_hb  [BT*HIDDEN];
__device__ float g_cos [Tn*HD];
__device__ float g_sin [Tn*HD];

// ---------------- weight conversion fp32 -> bf16 --------------------------------
__global__ void cvt_weights_kernel(const float* Wq, const float* Wk, const float* Wv,
                                   const float* Wg, const float* Wo, const float* w1,
                                   const float* w3, const float* w2,
                                   __nv_bfloat16* __restrict__ dst) {
    int idx = (blockIdx.x*blockDim.x + threadIdx.x) * 4;
    if (idx >= WTOT) return;
    const float* src; int off;
    if (idx < WOFF_O) {
        int r = idx >> 18;
        src = (r==0) ? Wq : (r==1) ? Wk : (r==2) ? Wv : Wg;
        off = idx & 262143;
    } else if (idx < WOFF_1) { src = Wo; off = idx - WOFF_O; }
    else if (idx < WOFF_3)   { src = w1; off = idx - WOFF_1; }
    else if (idx < WOFF_2)   { src = w3; off = idx - WOFF_3; }
    else                     { src = w2; off = idx - WOFF_2; }
    float4 v = *(const float4*)(src + off);
    union { __nv_bfloat162 h[2]; uint2 u; } pk;
    pk.h[0] = __floats2bfloat162_rn(v.x, v.y);
    pk.h[1] = __floats2bfloat162_rn(v.z, v.w);
    *(uint2*)(dst + idx) = pk.u;
}

// ---------------- RoPE tables --------------------------------------------------
__global__ void rope_init_kernel(float* __restrict__ c, float* __restrict__ s) {
    int t = blockIdx.x, d = threadIdx.x;   // d in [0,64)
    int i = d & 31;
    float invf = powf(10000.f, -(float)i * (1.f/32.f));
    float ph = (float)t * invf;
    c[t*HD + d] = cosf(ph);
    s[t*HD + d] = sinf(ph);
}

// ---------------- LayerNorm -> bf16 (row per block, 128 threads) ----------------
__global__ void ln_kernel(const float* __restrict__ x, const float* __restrict__ g,
                          const float* __restrict__ b, __nv_bfloat16* __restrict__ y) {
    int row = blockIdx.x;
    int tid = threadIdx.x;
    const float4* xr = (const float4*)(x + (size_t)row*D_MODEL);
    float4 v = xr[tid];
    float s  = v.x + v.y + v.z + v.w;
    float ss = v.x*v.x + v.y*v.y + v.z*v.z + v.w*v.w;
    __shared__ float r0[4], r1[4];
    #pragma unroll
    for (int o = 16; o; o >>= 1) {
        s  += __shfl_xor_sync(0xFFFFFFFFu, s,  o);
        ss += __shfl_xor_sync(0xFFFFFFFFu, ss, o);
    }
    if ((tid & 31) == 0) { r0[tid>>5] = s; r1[tid>>5] = ss; }
    __syncthreads();
    s  = r0[0] + r0[1] + r0[2] + r0[3];
    ss = r1[0] + r1[1] + r1[2] + r1[3];
    float mu  = s  * (1.f/D_MODEL);
    float var = ss * (1.f/D_MODEL) - mu*mu;
    float inv = rsqrtf(var + 1e-5f);
    float4 gg = ((const float4*)g)[tid];
    float4 bb = ((const float4*)b)[tid];
    float ox = (v.x-mu)*inv*gg.x + bb.x;
    float oy = (v.y-mu)*inv*gg.y + bb.y;
    float oz = (v.z-mu)*inv*gg.z + bb.z;
    float ow = (v.w-mu)*inv*gg.w + bb.w;
    union { __nv_bfloat162 h[2]; uint2 u; } pk;
    pk.h[0] = __floats2bfloat162_rn(ox, oy);
    pk.h[1] = __floats2bfloat162_rn(oz, ow);
    *(uint2*)(y + (size_t)row*D_MODEL + tid*4) = pk.u;
}

// ---------------- bf16 tensor-core GEMM (templated N-tile, multi-weight) -------
// C(fp32) = A(bf16)[M,K] @ W(bf16)[K,Nw] (+bias) (+res). Up to 4 weights fused
// along N. BM=128, BK=32, 256 thr. ldmatrix + mma.m16n8k16.
#define BM 128

__device__ __forceinline__ void cp16(uint32_t saddr, const void* gptr, int srcsz) {
    asm volatile("cp.async.cg.shared.global [%0], [%1], 16, %2;"
                 :: "r"(saddr), "l"(gptr), "r"(srcsz));
}
__device__ __forceinline__ void ldsm4(uint32_t* r, uint32_t addr) {
    asm volatile("ldmatrix.sync.aligned.m8n8.x4.shared.b16 {%0,%1,%2,%3}, [%4];"
                 : "=r"(r[0]), "=r"(r[1]), "=r"(r[2]), "=r"(r[3]) : "r"(addr));
}
__device__ __forceinline__ void ldsm4t(uint32_t* r, uint32_t addr) {
    asm volatile("ldmatrix.sync.aligned.m8n8.x4.trans.shared.b16 {%0,%1,%2,%3}, [%4];"
                 : "=r"(r[0]), "=r"(r[1]), "=r"(r[2]), "=r"(r[3]) : "r"(addr));
}
__device__ __forceinline__ void mma_bf16(float* c, const uint32_t* a, const uint32_t* b) {
    asm volatile("mma.sync.aligned.m16n8k16.row.col.f32.bf16.bf16.f32 "
                 "{%0,%1,%2,%3}, {%4,%5,%6,%7}, {%8,%9}, {%0,%1,%2,%3};"
                 : "+f"(c[0]), "+f"(c[1]), "+f"(c[2]), "+f"(c[3])
                 : "r"(a[0]), "r"(a[1]), "r"(a[2]), "r"(a[3]),
                   "r"(b[0]), "r"(b[1]));
}

template<int BNt>
__global__ __launch_bounds__(256)
void gemm_bf16(const __nv_bfloat16* __restrict__ A,
               const __nv_bfloat16* W0, const __nv_bfloat16* W1,
               const __nv_bfloat16* W2, const __nv_bfloat16* W3,
               const float* b0, const float* b1, const float* b2, const float* b3,
               const float* __restrict__ res,
               float* C0, float* C1, float* C2, float* C3,
               int M, int Nw, int K) {
    constexpr int BKt  = 32;
    constexpr int ASTR = 40;            // halves; row stride 80B (conflict-free ldsm)
    constexpr int BSTR = BNt + 24;      // halves; row stride/16B odd -> conflict-free
    constexpr int WR = (BNt == 128) ? 2 : 4;
    constexpr int WC = 8 / WR;
    constexpr int MI = BM / WR / 16;    // 4 or 2
    constexpr int NI = BNt / WC / 8;    // 4
    constexpr int LA  = (BM*BKt/8)/256; // 2
    constexpr int LB2 = (BKt*BNt/8)/256;// 2 or 1

    __shared__ __align__(16) __nv_bfloat16 As[2][BM*ASTR];
    __shared__ __align__(16) __nv_bfloat16 Bs[2][BKt*BSTR];

    int tid = threadIdx.x;
    int bm = blockIdx.y * BM;
    int gcol0 = blockIdx.x * BNt;
    int widx = gcol0 / Nw;
    int bn = gcol0 - widx * Nw;
    const __nv_bfloat16* W = (widx==0) ? W0 : (widx==1) ? W1 : (widx==2) ? W2 : W3;
    const float* bias      = (widx==0) ? b0 : (widx==1) ? b1 : (widx==2) ? b2 : b3;
    float*       C         = (widx==0) ? C0 : (widx==1) ? C1 : (widx==2) ? C2 : C3;

    int wid = tid >> 5, lane = tid & 31;
    int wm = wid % WR, wn = wid / WR;
    int gid = lane >> 2, tig = lane & 3;

    uint32_t asAddr = (uint32_t)__cvta_generic_to_shared(&As[0][0]);
    uint32_t bsAddr = (uint32_t)__cvta_generic_to_shared(&Bs[0][0]);

    // per-thread ldmatrix offsets (halves)
    int lr  = lane & 15;                // row within 16-row frag
    int lhi = (lane >> 4) << 3;         // 0 or 8
    int aoff = (wm*(BM/WR) + lr)*ASTR + lhi;
    int boff = lr*BSTR + wn*(BNt/WC) + lhi;

    float acc[MI][NI][4];
    #pragma unroll
    for (int i = 0; i < MI; i++)
        #pragma unroll
        for (int j = 0; j < NI; j++)
            #pragma unroll
            for (int r = 0; r < 4; r++) acc[i][j][r] = 0.f;

    const int KT = K / BKt;

    auto load_stage = [&](int kt, int stg) {
        int k0 = kt * BKt;
        #pragma unroll
        for (int i = 0; i < LA; i++) {
            int id = i*256 + tid;
            int arow = id >> 2;
            int ac = (id & 3) * 8;
            uint32_t sa = asAddr + (uint32_t)(stg*(BM*ASTR*2) + (arow*ASTR + ac)*2);
            const __nv_bfloat16* gp = A + (size_t)(bm + arow)*K + k0 + ac;
            cp16(sa, gp, (bm + arow < M) ? 16 : 0);
        }
        #pragma unroll
        for (int i = 0; i < LB2; i++) {
            int id = i*256 + tid;
            int brow = id / (BNt/8);
            int bc = (id % (BNt/8)) * 8;
            uint32_t sb = bsAddr + (uint32_t)(stg*(BKt*BSTR*2) + (brow*BSTR + bc)*2);
            const __nv_bfloat16* gp = W + (size_t)(k0 + brow)*Nw + bn + bc;
            cp16(sb, gp, 16);
        }
        asm volatile("cp.async.commit_group;");
    };

    load_stage(0, 0);

    for (int kt = 0; kt < KT; kt++) {
        int stg = kt & 1;
        if (kt + 1 < KT) {
            load_stage(kt + 1, stg ^ 1);
            asm volatile("cp.async.wait_group 1;");
        } else {
            asm volatile("cp.async.wait_group 0;");
        }
        __syncthreads();

        uint32_t aB = asAddr + (uint32_t)(stg*(BM*ASTR*2));
        uint32_t bB = bsAddr + (uint32_t)(stg*(BKt*BSTR*2));
        #pragma unroll
        for (int ks = 0; ks < BKt; ks += 16) {
            uint32_t af[MI][4], bf[NI][2];
            #pragma unroll
            for (int mi = 0; mi < MI; mi++)
                ldsm4(af[mi], aB + (uint32_t)((aoff + mi*16*ASTR + ks)*2));
            #pragma unroll
            for (int n2 = 0; n2 < NI/2; n2++) {
                uint32_t t[4];
                ldsm4t(t, bB + (uint32_t)((boff + ks*BSTR + n2*16)*2));
                bf[2*n2][0]   = t[0]; bf[2*n2][1]   = t[1];
                bf[2*n2+1][0] = t[2]; bf[2*n2+1][1] = t[3];
            }
            #pragma unroll
            for (int mi = 0; mi < MI; mi++)
                #pragma unroll
                for (int ni = 0; ni < NI; ni++)
                    mma_bf16(acc[mi][ni], af[mi], bf[ni]);
        }
        __syncthreads();
    }

    // epilogue (fp32)
    #pragma unroll
    for (int mi = 0; mi < MI; mi++) {
        int row0 = bm + wm*(BM/WR) + mi*16 + gid;
        #pragma unroll
        for (int ni = 0; ni < NI; ni++) {
            int col = bn + wn*(BNt/WC) + ni*8 + tig*2;
            float bb0 = bias ? bias[col]   : 0.f;
            float bb1 = bias ? bias[col+1] : 0.f;
            if (row0 < M) {
                float v0 = acc[mi][ni][0] + bb0;
                float v1 = acc[mi][ni][1] + bb1;
                if (res) { v0 += res[(size_t)row0*Nw + col]; v1 += res[(size_t)row0*Nw + col+1]; }
                *(float2*)(C + (size_t)row0*Nw + col) = make_float2(v0, v1);
            }
            int row1 = row0 + 8;
            if (row1 < M) {
                float v0 = acc[mi][ni][2] + bb0;
                float v1 = acc[mi][ni][3] + bb1;
                if (res) { v0 += res[(size_t)row1*Nw + col]; v1 += res[(size_t)row1*Nw + col+1]; }
                *(float2*)(C + (size_t)row1*Nw + col) = make_float2(v0, v1);
            }
        }
    }
}

// ---------------- RoPE apply (in place, q & k) ----------------------------------
__global__ void rope_apply_kernel(float* __restrict__ q, float* __restrict__ k,
                                  const float* __restrict__ cosb,
                                  const float* __restrict__ sinb) {
    int t = blockIdx.x, b = blockIdx.y;
    int tid = threadIdx.x;                 // 512 = h*64+d
    int d = tid & 63;
    size_t base  = ((size_t)b*Tn + t)*D_MODEL + tid;
    size_t pbase = ((size_t)b*Tn + t)*D_MODEL + (tid & ~63) + ((d < 32) ? d + 32 : d - 32);
    float c = cosb[t*HD + d], s = sinb[t*HD + d];
    float qv = q[base],  kv = k[base];
    float qp = q[pbase], kp = k[pbase];
    float sg = (d < 32) ? -1.f : 1.f;
    __syncthreads();
    q[base] = qv*c + sg*qp*s;
    k[base] = kv*c + sg*kp*s;
}

// ---------------- mask predicate ------------------------------------------------
__device__ __forceinline__ bool allowed_fn(int qi, int j, int s0, int s1) {
    int qd = (qi < L0c) ? 0 : (qi < LTc ? 1 : (qi < CLSc ? 2 : 3));
    if (j < L0c)       return (j < s0)          && ((qd == 0 && j <= qi) || qd >= 2);
    else if (j < LTc)  return ((j - L0c) < s1)  && ((qd == 1 && j <= qi) || qd >= 2);
    else if (j < CLSc) return true;
    else               return qd == 3;
}

// ---------------- attention (gate fused, bf16 output) ---------------------------
__global__ __launch_bounds__(256)
void attn_kernel(const float* __restrict__ q, const float* __restrict__ k,
                 const float* __restrict__ v, const float* __restrict__ gate,
                 const int* __restrict__ sl0p, const int* __restrict__ sl1p,
                 __nv_bfloat16* __restrict__ o) {
    int qb = blockIdx.x, h = blockIdx.y, b = blockIdx.z;
    int tid = threadIdx.x;
    __shared__ float qs[32][68];
    __shared__ float ks[32][68];
    __shared__ float vs[32][68];
    __shared__ float ps[32][33];
    const int s0 = sl0p[b], s1 = sl1p[b];
    const size_t hb = (size_t)b * Tn * D_MODEL + (size_t)h * HD;
    int q0 = qb * 32;
    int qmax = q0 + 31;
    int qd = (q0 < L0c) ? 0 : (q0 < LTc ? 1 : 2);

    {
        int r = tid >> 3, c4 = (tid & 7) * 8;
        int qi = q0 + r;
        float4 z = make_float4(0.f,0.f,0.f,0.f);
        if (qi < Tn) {
            const float4* src = (const float4*)(q + hb + (size_t)qi*D_MODEL + c4);
            *(float4*)&qs[r][c4]     = src[0];
            *(float4*)&qs[r][c4 + 4] = src[1];
        } else {
            *(float4*)&qs[r][c4]     = z;
            *(float4*)&qs[r][c4 + 4] = z;
        }
    }

    int row = tid >> 3;
    int kc  = tid & 7;
    int dg  = (tid & 7) * 8;
    int myq = q0 + row;
    float m_run = -1e30f, l_run = 0.f;
    float acc[8];
    #pragma unroll
    for (int i = 0; i < 8; i++) acc[i] = 0.f;

    for (int c0 = 0; c0 < Tn; c0 += 32) {
        bool keep;
        if (c0 >= LTc) {
            keep = true;
        } else if (c0 < L0c) {
            keep = (qd == 0) ? (c0 <= qmax && c0 < s0)
                 : (qd == 2) ? (c0 < s0) : false;
        } else {
            keep = (qd == 1) ? (c0 <= qmax && (c0 - L0c) < s1)
                 : (qd == 2) ? ((c0 - L0c) < s1) : false;
        }
        if (!keep) continue;

        {
            int r = tid >> 3, c4 = (tid & 7) * 8;
            int j = c0 + r;
            float4 z = make_float4(0.f,0.f,0.f,0.f);
            if (j < Tn) {
                const float4* ksrc = (const float4*)(k + hb + (size_t)j*D_MODEL + c4);
                const float4* vsrc = (const float4*)(v + hb + (size_t)j*D_MODEL + c4);
                *(float4*)&ks[r][c4]     = ksrc[0];
                *(float4*)&ks[r][c4 + 4] = ksrc[1];
                *(float4*)&vs[r][c4]     = vsrc[0];
                *(float4*)&vs[r][c4 + 4] = vsrc[1];
            } else {
                *(float4*)&ks[r][c4] = z; *(float4*)&ks[r][c4+4] = z;
                *(float4*)&vs[r][c4] = z; *(float4*)&vs[r][c4+4] = z;
            }
        }
        __syncthreads();

        float dot[4] = {0.f, 0.f, 0.f, 0.f};
        #pragma unroll
        for (int i2 = 0; i2 < 16; i2++) {
            float4 qv = *(const float4*)&qs[row][i2*4];
            #pragma unroll
            for (int u = 0; u < 4; u++) {
                float4 kv = *(const float4*)&ks[kc + u*8][i2*4];
                dot[u] += qv.x*kv.x + qv.y*kv.y + qv.z*kv.z + qv.w*kv.w;
            }
        }
        float sreg[4];
        #pragma unroll
        for (int u = 0; u < 4; u++) {
            int j = c0 + kc + u*8;
            bool ok = (j < Tn) && (myq < Tn) && allowed_fn(myq, j, s0, s1);
            sreg[u] = ok ? dot[u] * 0.125f : -1e9f;
        }
        float cmax = fmaxf(fmaxf(sreg[0], sreg[1]), fmaxf(sreg[2], sreg[3]));
        #pragma unroll
        for (int ofs = 4; ofs; ofs >>= 1)
            cmax = fmaxf(cmax, __shfl_xor_sync(0xFFFFFFFFu, cmax, ofs));
        float m_new = fmaxf(m_run, cmax);
        float scale = __expf(m_run - m_new);
        float csum = 0.f;
        #pragma unroll
        for (int u = 0; u < 4; u++) {
            float p = __expf(sreg[u] - m_new);
            csum += p;
            ps[row][kc + u*8] = p;
        }
        #pragma unroll
        for (int ofs = 4; ofs; ofs >>= 1)
            csum += __shfl_xor_sync(0xFFFFFFFFu, csum, ofs);
        l_run = l_run * scale + csum;
        m_run = m_new;
        __syncwarp();

        #pragma unroll
        for (int i = 0; i < 8; i++) acc[i] *= scale;
        for (int jj = 0; jj < 32; jj++) {
            float p = ps[row][jj];
            float4 v0 = *(const float4*)&vs[jj][dg];
            float4 v1 = *(const float4*)&vs[jj][dg + 4];
            acc[0] += p*v0.x; acc[1] += p*v0.y; acc[2] += p*v0.z; acc[3] += p*v0.w;
            acc[4] += p*v1.x; acc[5] += p*v1.y; acc[6] += p*v1.z; acc[7] += p*v1.w;
        }
        __syncthreads();
    }

    if (myq < Tn) {
        float inv = 1.f / l_run;
        size_t off = hb + (size_t)myq*D_MODEL + dg;
        float4 ga = *(const float4*)(gate + off);
        float4 gb = *(const float4*)(gate + off + 4);
        union { __nv_bfloat162 h[4]; uint4 u; } pk;
        pk.h[0] = __floats2bfloat162_rn(acc[0]*inv*ga.x, acc[1]*inv*ga.y);
        pk.h[1] = __floats2bfloat162_rn(acc[2]*inv*ga.z, acc[3]*inv*ga.w);
        pk.h[2] = __floats2bfloat162_rn(acc[4]*inv*gb.x, acc[5]*inv*gb.y);
        pk.h[3] = __floats2bfloat162_rn(acc[6]*inv*gb.z, acc[7]*inv*gb.w);
        *(uint4*)(o + off) = pk.u;
    }
}

// ---------------- elementwise: silu(a)*b -> bf16 --------------------------------
__global__ void silu_mul_kernel(const float* __restrict__ a, const float* __restrict__ b,
                                __nv_bfloat16* __restrict__ d, int n4) {
    int i = blockIdx.x*blockDim.x + threadIdx.x;
    if (i >= n4) return;
    float4 x = ((const float4*)a)[i]; float4 y = ((const float4*)b)[i];
    float rx = x.x / (1.f + __expf(-x.x)) * y.x;
    float ry = x.y / (1.f + __expf(-x.y)) * y.y;
    float rz = x.z / (1.f + __expf(-x.z)) * y.z;
    float rw = x.w / (1.f + __expf(-x.w)) * y.w;
    union { __nv_bfloat162 h[2]; uint2 u; } pk;
    pk.h[0] = __floats2bfloat162_rn(rx, ry);
    pk.h[1] = __floats2bfloat162_rn(rz, rw);
    *(uint2*)(d + (size_t)i*4) = pk.u;
}

// ---------------- launch -------------------------------------------------------
extern "C" void kernel_launch(void* const* d_in, const int* in_sizes, int n_in,
                              void* d_out, int out_size) {
    const float* x    = (const float*)d_in[0];
    const float* Wq   = (const float*)d_in[1];
    const float* bq   = (const float*)d_in[2];
    const float* Wk   = (const float*)d_in[3];
    const float* bk   = (const float*)d_in[4];
    const float* Wv   = (const float*)d_in[5];
    const float* bv   = (const float*)d_in[6];
    const float* Wo   = (const float*)d_in[7];
    const float* bo   = (const float*)d_in[8];
    const float* Wg   = (const float*)d_in[9];
    const float* bg   = (const float*)d_in[10];
    const float* ln1g = (const float*)d_in[11];
    const float* ln1b = (const float*)d_in[12];
    const float* w1   = (const float*)d_in[13];
    const float* w3   = (const float*)d_in[14];
    const float* w2   = (const float*)d_in[15];
    const float* ln2g = (const float*)d_in[16];
    const float* ln2b = (const float*)d_in[17];
    const int*   sl0  = (const int*)d_in[18];
    const int*   sl1  = (const int*)d_in[19];
    float* out = (float*)d_out;

    __nv_bfloat16 *wbf, *xnb, *xn2b, *obb, *hab;
    float *qb_, *kb_, *vb_, *gate, *x1, *ha, *hb2, *cosb, *sinb;
    cudaGetSymbolAddress((void**)&wbf,  g_wbf);
    cudaGetSymbolAddress((void**)&xnb,  g_xnb);
    cudaGetSymbolAddress((void**)&xn2b, g_xn2b);
    cudaGetSymbolAddress((void**)&obb,  g_obb);
    cudaGetSymbolAddress((void**)&hab,  g_hab);
    cudaGetSymbolAddress((void**)&qb_,  g_q);
    cudaGetSymbolAddress((void**)&kb_,  g_k);
    cudaGetSymbolAddress((void**)&vb_,  g_v);
    cudaGetSymbolAddress((void**)&gate, g_gate);
    cudaGetSymbolAddress((void**)&x1,   g_x1);
    cudaGetSymbolAddress((void**)&ha,   g_ha);
    cudaGetSymbolAddress((void**)&hb2,  g_hb);
    cudaGetSymbolAddress((void**)&cosb, g_cos);
    cudaGetSymbolAddress((void**)&sinb, g_sin);

    cvt_weights_kernel<<<WTOT/4/256, 256>>>(Wq, Wk, Wv, Wg, Wo, w1, w3, w2, wbf);
    rope_init_kernel<<<Tn, HD>>>(cosb, sinb);
    ln_kernel<<<BT, 128>>>(x, ln1g, ln1b, xnb);

    const int MB = (BT + BM - 1) / BM;             // 49

    // fused Q,K,V,gate GEMM: effective N = 2048, grid (16, 49)
    gemm_bf16<128><<<dim3(16, MB), 256>>>(
        xnb, wbf+WOFF_Q, wbf+WOFF_K, wbf+WOFF_V, wbf+WOFF_G,
        bq, bk, bv, bg, nullptr,
        qb_, kb_, vb_, gate, BT, D_MODEL, D_MODEL);

    rope_apply_kernel<<<dim3(Tn, Bn), 512>>>(qb_, kb_, cosb, sinb);

    attn_kernel<<<dim3((Tn + 31)/32, NHEAD, Bn), 256>>>(qb_, kb_, vb_, gate, sl0, sl1, obb);

    // Wo GEMM: BN=64, grid (8, 49)
    gemm_bf16<64><<<dim3(8, MB), 256>>>(
        obb, wbf+WOFF_O, wbf+WOFF_O, wbf+WOFF_O, wbf+WOFF_O,
        bo, bo, bo, bo, x,
        x1, x1, x1, x1, BT, D_MODEL, D_MODEL);

    ln_kernel<<<BT, 128>>>(x1, ln2g, ln2b, xn2b);

    // fused w1,w3 GEMM: effective N = 4096, grid (32, 49)
    gemm_bf16<128><<<dim3(32, MB), 256>>>(
        xn2b, wbf+WOFF_1, wbf+WOFF_3, wbf+WOFF_1, wbf+WOFF_3,
        nullptr, nullptr, nullptr, nullptr, nullptr,
        ha, hb2, ha, hb2, BT, HIDDEN, D_MODEL);

    silu_mul_kernel<<<(BT*HIDDEN/4 + 255)/256, 256>>>(ha, hb2, hab, BT*HIDDEN/4);

    // w2 GEMM: K=2048, BN=64, grid (8, 49)
    gemm_bf16<64><<<dim3(8, MB), 256>>>(
        hab, wbf+WOFF_2, wbf+WOFF_2, wbf+WOFF_2, wbf+WOFF_2,
        nullptr, nullptr, nullptr, nullptr, x1,
        out, out, out, out, BT, D_MODEL, HIDDEN);
}

// round 5
// speedup vs baseline: 10.2675x; 2.4361x over previous
#include <cuda_runtime.h>
#include <cuda_bf16.h>
#include <math.h>
#include <stdint.h>

#define D_MODEL 512
#define NHEAD   8
#define HD      64
#define Tn      1552
#define Bn      4
#define BT      (Bn*Tn)     // 6208
#define HIDDEN  2048
#define L0c     1024
#define LTc     1536
#define CLSc    1551

// weight bf16 buffer offsets (in elements)
#define WOFF_Q  0
#define WOFF_K  262144
#define WOFF_V  524288
#define WOFF_G  786432
#define WOFF_O  1048576
#define WOFF_1  1310720
#define WOFF_3  2359296
#define WOFF_2  3407872
#define WTOT    4456448

// ---------------- scratch -------------------------------------------------------
__device__ __nv_bfloat16 g_wbf [WTOT];
__device__ __nv_bfloat16 g_xnb [BT*D_MODEL];
__device__ __nv_bfloat16 g_xn2b[BT*D_MODEL];
__device__ __nv_bfloat16 g_obb [BT*D_MODEL];
__device__ __nv_bfloat16 g_hab [BT*HIDDEN];
__device__ __nv_bfloat16 g_qb  [BT*D_MODEL];
__device__ __nv_bfloat16 g_kb  [BT*D_MODEL];
__device__ __nv_bfloat16 g_vb  [BT*D_MODEL];
__device__ float g_q   [BT*D_MODEL];
__device__ float g_k   [BT*D_MODEL];
__device__ float g_v   [BT*D_MODEL];
__device__ float g_gate[BT*D_MODEL];
__device__ float g_x1  [BT*D_MODEL];
__device__ float g_ha  [BT*HIDDEN];
__device__ float g_hb  [BT*HIDDEN];
__device__ float g_cos [Tn*HD];
__device__ float g_sin [Tn*HD];

// ---------------- weight conversion fp32 -> bf16 --------------------------------
__global__ void cvt_weights_kernel(const float* Wq, const float* Wk, const float* Wv,
                                   const float* Wg, const float* Wo, const float* w1,
                                   const float* w3, const float* w2,
                                   __nv_bfloat16* __restrict__ dst) {
    int idx = (blockIdx.x*blockDim.x + threadIdx.x) * 4;
    if (idx >= WTOT) return;
    const float* src; int off;
    if (idx < WOFF_O) {
        int r = idx >> 18;
        src = (r==0) ? Wq : (r==1) ? Wk : (r==2) ? Wv : Wg;
        off = idx & 262143;
    } else if (idx < WOFF_1) { src = Wo; off = idx - WOFF_O; }
    else if (idx < WOFF_3)   { src = w1; off = idx - WOFF_1; }
    else if (idx < WOFF_2)   { src = w3; off = idx - WOFF_3; }
    else                     { src = w2; off = idx - WOFF_2; }
    float4 v = *(const float4*)(src + off);
    union { __nv_bfloat162 h[2]; uint2 u; } pk;
    pk.h[0] = __floats2bfloat162_rn(v.x, v.y);
    pk.h[1] = __floats2bfloat162_rn(v.z, v.w);
    *(uint2*)(dst + idx) = pk.u;
}

// ---------------- RoPE tables --------------------------------------------------
__global__ void rope_init_kernel(float* __restrict__ c, float* __restrict__ s) {
    int t = blockIdx.x, d = threadIdx.x;
    int i = d & 31;
    float invf = powf(10000.f, -(float)i * (1.f/32.f));
    float ph = (float)t * invf;
    c[t*HD + d] = cosf(ph);
    s[t*HD + d] = sinf(ph);
}

// ---------------- LayerNorm -> bf16 ---------------------------------------------
__global__ void ln_kernel(const float* __restrict__ x, const float* __restrict__ g,
                          const float* __restrict__ b, __nv_bfloat16* __restrict__ y) {
    int row = blockIdx.x;
    int tid = threadIdx.x;
    const float4* xr = (const float4*)(x + (size_t)row*D_MODEL);
    float4 v = xr[tid];
    float s  = v.x + v.y + v.z + v.w;
    float ss = v.x*v.x + v.y*v.y + v.z*v.z + v.w*v.w;
    __shared__ float r0[4], r1[4];
    #pragma unroll
    for (int o = 16; o; o >>= 1) {
        s  += __shfl_xor_sync(0xFFFFFFFFu, s,  o);
        ss += __shfl_xor_sync(0xFFFFFFFFu, ss, o);
    }
    if ((tid & 31) == 0) { r0[tid>>5] = s; r1[tid>>5] = ss; }
    __syncthreads();
    s  = r0[0] + r0[1] + r0[2] + r0[3];
    ss = r1[0] + r1[1] + r1[2] + r1[3];
    float mu  = s  * (1.f/D_MODEL);
    float var = ss * (1.f/D_MODEL) - mu*mu;
    float inv = rsqrtf(var + 1e-5f);
    float4 gg = ((const float4*)g)[tid];
    float4 bb = ((const float4*)b)[tid];
    float ox = (v.x-mu)*inv*gg.x + bb.x;
    float oy = (v.y-mu)*inv*gg.y + bb.y;
    float oz = (v.z-mu)*inv*gg.z + bb.z;
    float ow = (v.w-mu)*inv*gg.w + bb.w;
    union { __nv_bfloat162 h[2]; uint2 u; } pk;
    pk.h[0] = __floats2bfloat162_rn(ox, oy);
    pk.h[1] = __floats2bfloat162_rn(oz, ow);
    *(uint2*)(y + (size_t)row*D_MODEL + tid*4) = pk.u;
}

// ---------------- mma/ldmatrix helpers ------------------------------------------
__device__ __forceinline__ void cp16(uint32_t saddr, const void* gptr, int srcsz) {
    asm volatile("cp.async.cg.shared.global [%0], [%1], 16, %2;"
                 :: "r"(saddr), "l"(gptr), "r"(srcsz));
}
__device__ __forceinline__ void ldsm4(uint32_t* r, uint32_t addr) {
    asm volatile("ldmatrix.sync.aligned.m8n8.x4.shared.b16 {%0,%1,%2,%3}, [%4];"
                 : "=r"(r[0]), "=r"(r[1]), "=r"(r[2]), "=r"(r[3]) : "r"(addr));
}
__device__ __forceinline__ void ldsm4t(uint32_t* r, uint32_t addr) {
    asm volatile("ldmatrix.sync.aligned.m8n8.x4.trans.shared.b16 {%0,%1,%2,%3}, [%4];"
                 : "=r"(r[0]), "=r"(r[1]), "=r"(r[2]), "=r"(r[3]) : "r"(addr));
}
__device__ __forceinline__ void mma_bf16(float* c, const uint32_t* a, const uint32_t* b) {
    asm volatile("mma.sync.aligned.m16n8k16.row.col.f32.bf16.bf16.f32 "
                 "{%0,%1,%2,%3}, {%4,%5,%6,%7}, {%8,%9}, {%0,%1,%2,%3};"
                 : "+f"(c[0]), "+f"(c[1]), "+f"(c[2]), "+f"(c[3])
                 : "r"(a[0]), "r"(a[1]), "r"(a[2]), "r"(a[3]),
                   "r"(b[0]), "r"(b[1]));
}

// ---------------- bf16 GEMM: 3-stage cp.async pipeline --------------------------
#define BM 128
#define GST 3

template<int BNt>
__global__ __launch_bounds__(256)
void gemm_bf16(const __nv_bfloat16* __restrict__ A,
               const __nv_bfloat16* W0, const __nv_bfloat16* W1,
               const __nv_bfloat16* W2, const __nv_bfloat16* W3,
               const float* b0, const float* b1, const float* b2, const float* b3,
               const float* __restrict__ res,
               float* C0, float* C1, float* C2, float* C3,
               int M, int Nw, int K) {
    constexpr int BKt  = 32;
    constexpr int ASTR = 40;
    constexpr int BSTR = BNt + 8;
    constexpr int WR = (BNt == 128) ? 2 : 4;
    constexpr int WC = 8 / WR;
    constexpr int MI = BM / WR / 16;
    constexpr int NI = BNt / WC / 8;
    constexpr int LB2 = (BKt*BNt/8)/256;

    extern __shared__ __align__(16) char dyns[];
    __nv_bfloat16* As = (__nv_bfloat16*)dyns;                // GST * BM * ASTR
    __nv_bfloat16* Bs = As + GST*BM*ASTR;                    // GST * BKt * BSTR

    int tid = threadIdx.x;
    int bm = blockIdx.y * BM;
    int gcol0 = blockIdx.x * BNt;
    int widx = gcol0 / Nw;
    int bn = gcol0 - widx * Nw;
    const __nv_bfloat16* W = (widx==0) ? W0 : (widx==1) ? W1 : (widx==2) ? W2 : W3;
    const float* bias      = (widx==0) ? b0 : (widx==1) ? b1 : (widx==2) ? b2 : b3;
    float*       C         = (widx==0) ? C0 : (widx==1) ? C1 : (widx==2) ? C2 : C3;

    int wid = tid >> 5, lane = tid & 31;
    int wm = wid % WR, wn = wid / WR;
    int gid = lane >> 2, tig = lane & 3;

    uint32_t asAddr = (uint32_t)__cvta_generic_to_shared(As);
    uint32_t bsAddr = (uint32_t)__cvta_generic_to_shared(Bs);

    int lr  = lane & 15;
    int lhi = (lane >> 4) << 3;
    int aoff = (wm*(BM/WR) + lr)*ASTR + lhi;
    int boff = lr*BSTR + wn*(BNt/WC) + lhi;

    float acc[MI][NI][4];
    #pragma unroll
    for (int i = 0; i < MI; i++)
        #pragma unroll
        for (int j = 0; j < NI; j++)
            #pragma unroll
            for (int r = 0; r < 4; r++) acc[i][j][r] = 0.f;

    const int KT = K / BKt;

    auto load_stage = [&](int kt, int stg) {
        int k0 = kt * BKt;
        #pragma unroll
        for (int i = 0; i < 2; i++) {
            int id = i*256 + tid;
            int arow = id >> 2;
            int ac = (id & 3) * 8;
            uint32_t sa = asAddr + (uint32_t)((stg*BM*ASTR + arow*ASTR + ac)*2);
            const __nv_bfloat16* gp = A + (size_t)(bm + arow)*K + k0 + ac;
            cp16(sa, gp, (bm + arow < M) ? 16 : 0);
        }
        #pragma unroll
        for (int i = 0; i < LB2; i++) {
            int id = i*256 + tid;
            int brow = id / (BNt/8);
            int bc = (id % (BNt/8)) * 8;
            uint32_t sb = bsAddr + (uint32_t)((stg*BKt*BSTR + brow*BSTR + bc)*2);
            const __nv_bfloat16* gp = W + (size_t)(k0 + brow)*Nw + bn + bc;
            cp16(sb, gp, 16);
        }
        asm volatile("cp.async.commit_group;");
    };

    load_stage(0, 0);
    load_stage(1, 1);

    int stg = 0;
    for (int kt = 0; kt < KT; kt++) {
        if (kt + 2 < KT) {
            int s2 = stg + 2; if (s2 >= GST) s2 -= GST;
            load_stage(kt + 2, s2);
            asm volatile("cp.async.wait_group 2;");
        } else if (kt + 1 < KT) {
            asm volatile("cp.async.wait_group 1;");
        } else {
            asm volatile("cp.async.wait_group 0;");
        }
        __syncthreads();

        uint32_t aB = asAddr + (uint32_t)(stg*BM*ASTR*2);
        uint32_t bB = bsAddr + (uint32_t)(stg*BKt*BSTR*2);
        #pragma unroll
        for (int ks = 0; ks < BKt; ks += 16) {
            uint32_t af[MI][4], bf[NI][2];
            #pragma unroll
            for (int mi = 0; mi < MI; mi++)
                ldsm4(af[mi], aB + (uint32_t)((aoff + mi*16*ASTR + ks)*2));
            #pragma unroll
            for (int n2 = 0; n2 < NI/2; n2++) {
                uint32_t t[4];
                ldsm4t(t, bB + (uint32_t)((boff + ks*BSTR + n2*16)*2));
                bf[2*n2][0]   = t[0]; bf[2*n2][1]   = t[1];
                bf[2*n2+1][0] = t[2]; bf[2*n2+1][1] = t[3];
            }
            #pragma unroll
            for (int mi = 0; mi < MI; mi++)
                #pragma unroll
                for (int ni = 0; ni < NI; ni++)
                    mma_bf16(acc[mi][ni], af[mi], bf[ni]);
        }
        __syncthreads();
        stg++; if (stg >= GST) stg = 0;
    }

    #pragma unroll
    for (int mi = 0; mi < MI; mi++) {
        int row0 = bm + wm*(BM/WR) + mi*16 + gid;
        #pragma unroll
        for (int ni = 0; ni < NI; ni++) {
            int col = bn + wn*(BNt/WC) + ni*8 + tig*2;
            float bb0 = bias ? bias[col]   : 0.f;
            float bb1 = bias ? bias[col+1] : 0.f;
            if (row0 < M) {
                float v0 = acc[mi][ni][0] + bb0;
                float v1 = acc[mi][ni][1] + bb1;
                if (res) { v0 += res[(size_t)row0*Nw + col]; v1 += res[(size_t)row0*Nw + col+1]; }
                *(float2*)(C + (size_t)row0*Nw + col) = make_float2(v0, v1);
            }
            int row1 = row0 + 8;
            if (row1 < M) {
                float v0 = acc[mi][ni][2] + bb0;
                float v1 = acc[mi][ni][3] + bb1;
                if (res) { v0 += res[(size_t)row1*Nw + col]; v1 += res[(size_t)row1*Nw + col+1]; }
                *(float2*)(C + (size_t)row1*Nw + col) = make_float2(v0, v1);
            }
        }
    }
}

// ---------------- RoPE + cvt to bf16 (q scaled by 1/8) --------------------------
__global__ void rope_cvt_kernel(const float* __restrict__ q, const float* __restrict__ k,
                                const float* __restrict__ v,
                                const float* __restrict__ cosb, const float* __restrict__ sinb,
                                __nv_bfloat16* __restrict__ qo, __nv_bfloat16* __restrict__ ko,
                                __nv_bfloat16* __restrict__ vo) {
    int t = blockIdx.x, b = blockIdx.y;
    int tid = threadIdx.x;                 // 512 = h*64+d
    int d = tid & 63;
    size_t base  = ((size_t)b*Tn + t)*D_MODEL + tid;
    size_t pbase = ((size_t)b*Tn + t)*D_MODEL + (tid & ~63) + ((d < 32) ? d + 32 : d - 32);
    float c = cosb[t*HD + d], s = sinb[t*HD + d];
    float sg = (d < 32) ? -1.f : 1.f;
    float qv = q[base]*c + sg*q[pbase]*s;
    float kv = k[base]*c + sg*k[pbase]*s;
    qo[base] = __float2bfloat16(qv * 0.125f);
    ko[base] = __float2bfloat16(kv);
    vo[base] = __float2bfloat16(v[base]);
}

// ---------------- mask predicate ------------------------------------------------
__device__ __forceinline__ bool allowed2(int qi, int j, int s0, int s1) {
    if (j >= Tn) return false;
    int qd = (qi < L0c) ? 0 : (qi < LTc ? 1 : (qi < CLSc ? 2 : 3));
    if (j < L0c)  return (j < s0) && (qd >= 2 || (qd == 0 && j <= qi));
    if (j < LTc)  return ((j - L0c) < s1) && (qd >= 2 || (qd == 1 && j <= qi));
    if (j < CLSc) return true;
    return qd >= 3;
}

// ---------------- tensor-core attention (FA2 style, gate fused) -----------------
#define AQ 128
#define AC 64
#define QSTR 72

__global__ __launch_bounds__(256)
void attn_mma_kernel(const __nv_bfloat16* __restrict__ q,
                     const __nv_bfloat16* __restrict__ k,
                     const __nv_bfloat16* __restrict__ v,
                     const float* __restrict__ gate,
                     const int* __restrict__ sl0p, const int* __restrict__ sl1p,
                     __nv_bfloat16* __restrict__ o) {
    __shared__ __align__(16) __nv_bfloat16 kvs[2][2][AC*QSTR];
    int qb = blockIdx.x, h = blockIdx.y, b = blockIdx.z;
    int tid = threadIdx.x;
    int wid = tid >> 5, lane = tid & 31;
    int gid = lane >> 2, tig = lane & 3;
    int lr = lane & 15, lhi = (lane >> 4) << 3;
    const int s0 = sl0p[b], s1 = sl1p[b];
    const int q0 = qb * AQ, qmax = q0 + AQ - 1;
    const size_t rowbase = (size_t)b * Tn;
    const int hcol = h * HD;

    uint32_t smA = (uint32_t)__cvta_generic_to_shared(&kvs[0][0][0]);

    // ---- Q tile into kvs[0] region (exactly AQ*QSTR halves), then to frags ----
    #pragma unroll
    for (int i = 0; i < 4; i++) {
        int id = i*256 + tid;
        int r = id >> 3, cc = (id & 7) * 8;
        int qi = q0 + r;
        cp16(smA + (uint32_t)((r*QSTR + cc)*2),
             q + (rowbase + qi)*D_MODEL + hcol + cc, (qi < Tn) ? 16 : 0);
    }
    asm volatile("cp.async.commit_group;");
    asm volatile("cp.async.wait_group 0;");
    __syncthreads();

    uint32_t qf[4][4];
    {
        int qrow = wid * 16;
        #pragma unroll
        for (int kf = 0; kf < 4; kf++)
            ldsm4(qf[kf], smA + (uint32_t)(((qrow + lr)*QSTR + kf*16 + lhi)*2));
    }
    __syncthreads();

    auto keepf = [&](int c) -> bool {
        if (c >= LTc) return true;
        if (c < L0c) {
            if (qb < 8)  return (c <= qmax) && (c < s0);
            if (qb < 12) return false;
            return c < s0;
        } else {
            if (qb < 8)  return false;
            if (qb < 12) return (c <= qmax) && (c - L0c < s1);
            return (c - L0c) < s1;
        }
    };
    auto fullf = [&](int c) -> bool {
        if (qb < 8)  return (c < L0c)  && (c + AC - 1 <= q0) && (c + AC - 1 < s0);
        if (qb < 12) return (c >= L0c) && (c + AC - 1 <= q0) && (c + AC - 1 - L0c < s1);
        return false;
    };
    auto load_kv = [&](int c, int bufi) {
        #pragma unroll
        for (int i = 0; i < 2; i++) {
            int id = i*256 + tid;
            int r = id >> 3, cc = (id & 7) * 8;
            int j = c + r;
            cp16(smA + (uint32_t)(((bufi*2+0)*AC*QSTR + r*QSTR + cc)*2),
                 k + (rowbase + j)*D_MODEL + hcol + cc, (j < Tn) ? 16 : 0);
        }
        #pragma unroll
        for (int i = 0; i < 2; i++) {
            int id = i*256 + tid;
            int r = id >> 3, cc = (id & 7) * 8;
            int j = c + r;
            cp16(smA + (uint32_t)(((bufi*2+1)*AC*QSTR + r*QSTR + cc)*2),
                 v + (rowbase + j)*D_MODEL + hcol + cc, (j < Tn) ? 16 : 0);
        }
        asm volatile("cp.async.commit_group;");
    };

    float m0 = -1e30f, m1 = -1e30f, l0 = 0.f, l1 = 0.f;
    float oacc[8][4];
    #pragma unroll
    for (int n = 0; n < 8; n++)
        #pragma unroll
        for (int e = 0; e < 4; e++) oacc[n][e] = 0.f;

    const int CEND = 1600;
    int cur = 0;
    while (cur < CEND && !keepf(cur)) cur += AC;
    int buf = 0;
    load_kv(cur, 0);

    while (cur < CEND) {
        int nxt = cur + AC;
        while (nxt < CEND && !keepf(nxt)) nxt += AC;
        if (nxt < CEND) { load_kv(nxt, buf^1); asm volatile("cp.async.wait_group 1;"); }
        else            { asm volatile("cp.async.wait_group 0;"); }
        __syncthreads();

        uint32_t kA = smA + (uint32_t)((buf*2+0)*AC*QSTR*2);
        uint32_t vA = smA + (uint32_t)((buf*2+1)*AC*QSTR*2);

        // ---- S = Q @ K^T ----
        float sacc[8][4];
        #pragma unroll
        for (int n = 0; n < 8; n++)
            #pragma unroll
            for (int e = 0; e < 4; e++) sacc[n][e] = 0.f;
        #pragma unroll
        for (int kf = 0; kf < 4; kf++) {
            uint32_t kb[8][2];
            #pragma unroll
            for (int g = 0; g < 4; g++) {
                uint32_t t[4];
                ldsm4(t, kA + (uint32_t)(((g*16+lr)*QSTR + kf*16 + lhi)*2));
                kb[2*g][0]   = t[0]; kb[2*g][1]   = t[2];
                kb[2*g+1][0] = t[1]; kb[2*g+1][1] = t[3];
            }
            #pragma unroll
            for (int n = 0; n < 8; n++)
                mma_bf16(sacc[n], qf[kf], kb[n]);
        }

        // ---- mask ----
        if (!fullf(cur)) {
            int r0 = q0 + wid*16 + gid, r1 = r0 + 8;
            #pragma unroll
            for (int n = 0; n < 8; n++) {
                int j0 = cur + n*8 + tig*2, j1 = j0 + 1;
                if (!allowed2(r0, j0, s0, s1)) sacc[n][0] = -1e9f;
                if (!allowed2(r0, j1, s0, s1)) sacc[n][1] = -1e9f;
                if (!allowed2(r1, j0, s0, s1)) sacc[n][2] = -1e9f;
                if (!allowed2(r1, j1, s0, s1)) sacc[n][3] = -1e9f;
            }
        }

        // ---- online softmax ----
        float mx0 = -1e30f, mx1 = -1e30f;
        #pragma unroll
        for (int n = 0; n < 8; n++) {
            mx0 = fmaxf(mx0, fmaxf(sacc[n][0], sacc[n][1]));
            mx1 = fmaxf(mx1, fmaxf(sacc[n][2], sacc[n][3]));
        }
        mx0 = fmaxf(mx0, __shfl_xor_sync(0xFFFFFFFFu, mx0, 1));
        mx0 = fmaxf(mx0, __shfl_xor_sync(0xFFFFFFFFu, mx0, 2));
        mx1 = fmaxf(mx1, __shfl_xor_sync(0xFFFFFFFFu, mx1, 1));
        mx1 = fmaxf(mx1, __shfl_xor_sync(0xFFFFFFFFu, mx1, 2));
        float mn0 = fmaxf(m0, mx0), mn1 = fmaxf(m1, mx1);
        float sc0 = __expf(m0 - mn0), sc1 = __expf(m1 - mn1);
        m0 = mn0; m1 = mn1;

        uint32_t pa[8][2];
        float rs0 = 0.f, rs1 = 0.f;
        #pragma unroll
        for (int n = 0; n < 8; n++) {
            float p0 = __expf(sacc[n][0] - m0);
            float p1 = __expf(sacc[n][1] - m0);
            float p2 = __expf(sacc[n][2] - m1);
            float p3 = __expf(sacc[n][3] - m1);
            rs0 += p0 + p1; rs1 += p2 + p3;
            __nv_bfloat162 h0 = __floats2bfloat162_rn(p0, p1);
            __nv_bfloat162 h1 = __floats2bfloat162_rn(p2, p3);
            pa[n][0] = *(uint32_t*)&h0;
            pa[n][1] = *(uint32_t*)&h1;
        }
        l0 = l0*sc0 + rs0; l1 = l1*sc1 + rs1;
        #pragma unroll
        for (int n = 0; n < 8; n++) {
            oacc[n][0] *= sc0; oacc[n][1] *= sc0;
            oacc[n][2] *= sc1; oacc[n][3] *= sc1;
        }

        // ---- O += P @ V ----
        #pragma unroll
        for (int kf = 0; kf < 4; kf++) {
            uint32_t a[4] = { pa[2*kf][0], pa[2*kf][1], pa[2*kf+1][0], pa[2*kf+1][1] };
            #pragma unroll
            for (int n2 = 0; n2 < 4; n2++) {
                uint32_t t[4];
                ldsm4t(t, vA + (uint32_t)(((kf*16+lr)*QSTR + n2*16 + lhi)*2));
                uint32_t bb0[2] = {t[0], t[1]}, bb1[2] = {t[2], t[3]};
                mma_bf16(oacc[2*n2],   a, bb0);
                mma_bf16(oacc[2*n2+1], a, bb1);
            }
        }
        __syncthreads();
        cur = nxt; buf ^= 1;
    }

    // ---- epilogue: normalize, gate, write bf16 ----
    l0 += __shfl_xor_sync(0xFFFFFFFFu, l0, 1);
    l0 += __shfl_xor_sync(0xFFFFFFFFu, l0, 2);
    l1 += __shfl_xor_sync(0xFFFFFFFFu, l1, 1);
    l1 += __shfl_xor_sync(0xFFFFFFFFu, l1, 2);
    float inv0 = 1.f / l0, inv1 = 1.f / l1;
    int r0 = q0 + wid*16 + gid, r1 = r0 + 8;
    #pragma unroll
    for (int n = 0; n < 8; n++) {
        int col = hcol + n*8 + tig*2;
        if (r0 < Tn) {
            float2 g = *(const float2*)(gate + (rowbase + r0)*D_MODEL + col);
            __nv_bfloat162 pk = __floats2bfloat162_rn(oacc[n][0]*inv0*g.x,
                                                      oacc[n][1]*inv0*g.y);
            *(__nv_bfloat162*)(o + (rowbase + r0)*D_MODEL + col) = pk;
        }
        if (r1 < Tn) {
            float2 g = *(const float2*)(gate + (rowbase + r1)*D_MODEL + col);
            __nv_bfloat162 pk = __floats2bfloat162_rn(oacc[n][2]*inv1*g.x,
                                                      oacc[n][3]*inv1*g.y);
            *(__nv_bfloat162*)(o + (rowbase + r1)*D_MODEL + col) = pk;
        }
    }
}

// ---------------- elementwise: silu(a)*b -> bf16 --------------------------------
__global__ void silu_mul_kernel(const float* __restrict__ a, const float* __restrict__ b,
                                __nv_bfloat16* __restrict__ d, int n4) {
    int i = blockIdx.x*blockDim.x + threadIdx.x;
    if (i >= n4) return;
    float4 x = ((const float4*)a)[i]; float4 y = ((const float4*)b)[i];
    float rx = x.x / (1.f + __expf(-x.x)) * y.x;
    float ry = x.y / (1.f + __expf(-x.y)) * y.y;
    float rz = x.z / (1.f + __expf(-x.z)) * y.z;
    float rw = x.w / (1.f + __expf(-x.w)) * y.w;
    union { __nv_bfloat162 h[2]; uint2 u; } pk;
    pk.h[0] = __floats2bfloat162_rn(rx, ry);
    pk.h[1] = __floats2bfloat162_rn(rz, rw);
    *(uint2*)(d + (size_t)i*4) = pk.u;
}

// ---------------- launch -------------------------------------------------------
extern "C" void kernel_launch(void* const* d_in, const int* in_sizes, int n_in,
                              void* d_out, int out_size) {
    const float* x    = (const float*)d_in[0];
    const float* Wq   = (const float*)d_in[1];
    const float* bq   = (const float*)d_in[2];
    const float* Wk   = (const float*)d_in[3];
    const float* bk   = (const float*)d_in[4];
    const float* Wv   = (const float*)d_in[5];
    const float* bv   = (const float*)d_in[6];
    const float* Wo   = (const float*)d_in[7];
    const float* bo   = (const float*)d_in[8];
    const float* Wg   = (const float*)d_in[9];
    const float* bg   = (const float*)d_in[10];
    const float* ln1g = (const float*)d_in[11];
    const float* ln1b = (const float*)d_in[12];
    const float* w1   = (const float*)d_in[13];
    const float* w3   = (const float*)d_in[14];
    const float* w2   = (const float*)d_in[15];
    const float* ln2g = (const float*)d_in[16];
    const float* ln2b = (const float*)d_in[17];
    const int*   sl0  = (const int*)d_in[18];
    const int*   sl1  = (const int*)d_in[19];
    float* out = (float*)d_out;

    __nv_bfloat16 *wbf, *xnb, *xn2b, *obb, *hab, *qbb, *kbb, *vbb;
    float *qb_, *kb_, *vb_, *gate, *x1, *ha, *hb2, *cosb, *sinb;
    cudaGetSymbolAddress((void**)&wbf,  g_wbf);
    cudaGetSymbolAddress((void**)&xnb,  g_xnb);
    cudaGetSymbolAddress((void**)&xn2b, g_xn2b);
    cudaGetSymbolAddress((void**)&obb,  g_obb);
    cudaGetSymbolAddress((void**)&hab,  g_hab);
    cudaGetSymbolAddress((void**)&qbb,  g_qb);
    cudaGetSymbolAddress((void**)&kbb,  g_kb);
    cudaGetSymbolAddress((void**)&vbb,  g_vb);
    cudaGetSymbolAddress((void**)&qb_,  g_q);
    cudaGetSymbolAddress((void**)&kb_,  g_k);
    cudaGetSymbolAddress((void**)&vb_,  g_v);
    cudaGetSymbolAddress((void**)&gate, g_gate);
    cudaGetSymbolAddress((void**)&x1,   g_x1);
    cudaGetSymbolAddress((void**)&ha,   g_ha);
    cudaGetSymbolAddress((void**)&hb2,  g_hb);
    cudaGetSymbolAddress((void**)&cosb, g_cos);
    cudaGetSymbolAddress((void**)&sinb, g_sin);

    const int smem128 = GST*(BM*40 + 32*(128+8))*2;   // 56832
    const int smem64  = GST*(BM*40 + 32*(64+8))*2;    // 44544
    cudaFuncSetAttribute(gemm_bf16<128>, cudaFuncAttributeMaxDynamicSharedMemorySize, smem128);
    cudaFuncSetAttribute(gemm_bf16<64>,  cudaFuncAttributeMaxDynamicSharedMemorySize, smem64);

    cvt_weights_kernel<<<WTOT/4/256, 256>>>(Wq, Wk, Wv, Wg, Wo, w1, w3, w2, wbf);
    rope_init_kernel<<<Tn, HD>>>(cosb, sinb);
    ln_kernel<<<BT, 128>>>(x, ln1g, ln1b, xnb);

    const int MB = (BT + BM - 1) / BM;             // 49

    gemm_bf16<128><<<dim3(16, MB), 256, smem128>>>(
        xnb, wbf+WOFF_Q, wbf+WOFF_K, wbf+WOFF_V, wbf+WOFF_G,
        bq, bk, bv, bg, nullptr,
        qb_, kb_, vb_, gate, BT, D_MODEL, D_MODEL);

    rope_cvt_kernel<<<dim3(Tn, Bn), 512>>>(qb_, kb_, vb_, cosb, sinb, qbb, kbb, vbb);

    attn_mma_kernel<<<dim3(13, NHEAD, Bn), 256>>>(qbb, kbb, vbb, gate, sl0, sl1, obb);

    gemm_bf16<64><<<dim3(8, MB), 256, smem64>>>(
        obb, wbf+WOFF_O, wbf+WOFF_O, wbf+WOFF_O, wbf+WOFF_O,
        bo, bo, bo, bo, x,
        x1, x1, x1, x1, BT, D_MODEL, D_MODEL);

    ln_kernel<<<BT, 128>>>(x1, ln2g, ln2b, xn2b);

    gemm_bf16<128><<<dim3(32, MB), 256, smem128>>>(
        xn2b, wbf+WOFF_1, wbf+WOFF_3, wbf+WOFF_1, wbf+WOFF_3,
        nullptr, nullptr, nullptr, nullptr, nullptr,
        ha, hb2, ha, hb2, BT, HIDDEN, D_MODEL);

    silu_mul_kernel<<<(BT*HIDDEN/4 + 255)/256, 256>>>(ha, hb2, hab, BT*HIDDEN/4);

    gemm_bf16<64><<<dim3(8, MB), 256, smem64>>>(
        hab, wbf+WOFF_2, wbf+WOFF_2, wbf+WOFF_2, wbf+WOFF_2,
        nullptr, nullptr, nullptr, nullptr, x1,
        out, out, out, out, BT, D_MODEL, HIDDEN);
}